// round 3
// baseline (speedup 1.0000x reference)
#include <cuda_runtime.h>
#include <math.h>
#include <stdint.h>

#define BB 4
#define CC 256
#define HW 4096
#define K9 9
#define KK 2304   // 256*9
#define NG 32
#define CPG 8
#define BKT 16

// ---------------- static scratch ----------------
__device__ float g_t[BB * CC * HW];              // GN(conv1) output
__device__ float g_raw[BB * CC * HW];            // pre-GN conv outputs
__device__ uint32_t g_wT1[KK * 256];             // tf32 bits, [kk][oc]
__device__ uint32_t g_wT2[KK * 128];             // conv2 (18 out, padded 128)
__device__ uint32_t g_wTc[KK * 256];
__device__ uint32_t g_wTr[KK * 256];
__device__ uint32_t g_meta[(size_t)BB * K9 * 8 * HW];  // 4 idx + 4 weights per (b,k,m)
__device__ float g_mu[BB * NG];
__device__ float g_rstd[BB * NG];

__device__ __forceinline__ uint32_t f2tf32(float x) {
    uint32_t r;
    asm("cvt.rna.tf32.f32 %0, %1;" : "=r"(r) : "f"(x));
    return r;
}

__device__ __forceinline__ void mma_tf32(float* d, uint32_t a0, uint32_t a1,
                                         uint32_t a2, uint32_t a3,
                                         uint32_t b0, uint32_t b1) {
    asm volatile(
        "mma.sync.aligned.m16n8k8.row.col.f32.tf32.tf32.f32 "
        "{%0,%1,%2,%3}, {%4,%5,%6,%7}, {%8,%9}, {%0,%1,%2,%3};"
        : "+f"(d[0]), "+f"(d[1]), "+f"(d[2]), "+f"(d[3])
        : "r"(a0), "r"(a1), "r"(a2), "r"(a3), "r"(b0), "r"(b1));
}

// ---------------- weight transpose -> tf32: w[O][256][9] -> wT[(tap*256+ci)][o]
__global__ void transpose_w_tf32(const float* __restrict__ w, uint32_t* __restrict__ wT,
                                 int O, int ldo) {
    int i = blockIdx.x * 256 + threadIdx.x;
    if (i >= KK * ldo) return;
    int o = i % ldo;
    int kk = i / ldo;
    int ci = kk % CC;
    int tap = kk / CC;
    float v = (o < O) ? w[(o * CC + ci) * K9 + tap] : 0.f;
    wT[i] = f2tf32(v);
}

// ---------------- deform meta: per (b,k,m) -> 4 clamped indices + 4 weights
__global__ void deform_meta(const float* __restrict__ pts, uint32_t* __restrict__ meta) {
    int m = blockIdx.x * 256 + threadIdx.x;
    int k = blockIdx.y;
    int b = blockIdx.z;
    int y = m >> 6, x = m & 63;
    float pty = pts[(b * 18 + 2 * k) * HW + m];
    float ptx = pts[(b * 18 + 2 * k + 1) * HW + m];
    float bx = (float)(k - 4);
    float py = pty + (float)y;
    float px = ((ptx - bx) + (float)x) + bx;
    float y0f = floorf(py), x0f = floorf(px);
    int y0 = (int)y0f, x0 = (int)x0f;
    float wy = py - y0f, wx = px - x0f;
    float w00 = (1.f - wy) * (1.f - wx);
    float w01 = (1.f - wy) * wx;
    float w10 = wy * (1.f - wx);
    float w11 = wy * wx;
    bool vy0 = (y0 >= 0) && (y0 <= 63);
    bool vy1 = (y0 + 1 >= 0) && (y0 + 1 <= 63);
    bool vx0 = (x0 >= 0) && (x0 <= 63);
    bool vx1 = (x0 + 1 >= 0) && (x0 + 1 <= 63);
    w00 = (vy0 && vx0) ? w00 : 0.f;
    w01 = (vy0 && vx1) ? w01 : 0.f;
    w10 = (vy1 && vx0) ? w10 : 0.f;
    w11 = (vy1 && vx1) ? w11 : 0.f;
    int y0c = min(max(y0, 0), 63), y1c = min(max(y0 + 1, 0), 63);
    int x0c = min(max(x0, 0), 63), x1c = min(max(x0 + 1, 0), 63);
    uint32_t* mb = meta + (((size_t)(b * K9 + k)) << 15) + m;  // *8*4096
    mb[0 * HW] = (uint32_t)(y0c * 64 + x0c);
    mb[1 * HW] = (uint32_t)(y0c * 64 + x1c);
    mb[2 * HW] = (uint32_t)(y1c * 64 + x0c);
    mb[3 * HW] = (uint32_t)(y1c * 64 + x1c);
    mb[4 * HW] = __float_as_uint(w00);
    mb[5 * HW] = __float_as_uint(w01);
    mb[6 * HW] = __float_as_uint(w10);
    mb[7 * HW] = __float_as_uint(w11);
}

// ---------------- GroupNorm stats: one block per (b,g) --------------------
__global__ void gn_stats(const float* __restrict__ raw) {
    int bg = blockIdx.x;
    const float* p = raw + (size_t)bg * CPG * HW;
    float s = 0.f, ss = 0.f;
    for (int i = threadIdx.x; i < CPG * HW; i += 256) {
        float v = p[i];
        s += v; ss += v * v;
    }
    __shared__ float sh[512];
    sh[threadIdx.x] = s;
    sh[256 + threadIdx.x] = ss;
    __syncthreads();
    for (int o = 128; o > 0; o >>= 1) {
        if (threadIdx.x < o) {
            sh[threadIdx.x] += sh[threadIdx.x + o];
            sh[256 + threadIdx.x] += sh[256 + threadIdx.x + o];
        }
        __syncthreads();
    }
    if (threadIdx.x == 0) {
        const float inv_n = 1.f / (float)(CPG * HW);
        float mean = sh[0] * inv_n;
        float var = sh[256] * inv_n - mean * mean;
        g_mu[bg] = mean;
        g_rstd[bg] = rsqrtf(var + 1e-5f);
    }
}

__global__ void gn_apply(const float* __restrict__ raw,
                         const float* __restrict__ gamma,
                         const float* __restrict__ beta,
                         float* __restrict__ out) {
    int i = blockIdx.x * 256 + threadIdx.x;
    int c = (i >> 12) & 255;
    int bg = i >> 15;
    float v = (raw[i] - g_mu[bg]) * g_rstd[bg] * gamma[c] + beta[c];
    out[i] = fmaxf(v, 0.f);
}

// ---------------- fused implicit TF32 GEMM ---------------------------------
// C[b][n][m] = sum_kk A[b][kk][m] * Bw[kk][n]
// A built on the fly: MODE 0 = im2col(3x3,pad1) of img; MODE 1 = bilinear
// deform sampling of img using precomputed meta.
// BM=128, BN=NT (128 or 256), BK=16. warps 2 x (NT/64), 64x64 per warp.
template<int MODE, int NT>
__global__ void __launch_bounds__(NT, 1)
fgemm(const float* __restrict__ img, const uint32_t* __restrict__ Bw,
      const uint32_t* __restrict__ meta, float* __restrict__ Cout,
      const float* __restrict__ bias, int Nreal, int ldb, long cBatch) {
    constexpr int BN = NT;
    constexpr int MQ = NT / 16;        // m-positions per staging row
    constexpr int SREP = 128 / MQ;
    __shared__ uint32_t As[BKT * 128];
    __shared__ uint32_t Bs[BKT * BN];
    __shared__ uint32_t Ms[MODE ? 8 * 128 : 8];

    int bm = blockIdx.x * 128, b = blockIdx.z;
    int tid = threadIdx.x;
    int warp = tid >> 5, lane = tid & 31;
    int wm = (warp & 1) * 64, wn = (warp >> 1) * 64;
    int r = lane >> 2, c = lane & 3;
    int sk = tid / MQ;     // staging k row 0..15
    int sm = tid % MQ;
    const float* imgb = img + ((size_t)b << 20);   // b*256*4096

    float acc[4][8][4];
#pragma unroll
    for (int mt = 0; mt < 4; mt++)
#pragma unroll
        for (int nt = 0; nt < 8; nt++)
#pragma unroll
            for (int i = 0; i < 4; i++) acc[mt][nt][i] = 0.f;

    for (int k0 = 0; k0 < KK; k0 += BKT) {
        int tap = k0 >> 8;
        if (MODE == 1 && (k0 & 255) == 0) {
            // refresh per-tap meta slice for this block's 128 m values
            const uint32_t* mg = meta + (((size_t)(b * K9 + tap)) << 15);
#pragma unroll
            for (int i = tid; i < 1024; i += NT) {
                int f = i >> 7, mm = i & 127;
                Ms[i] = mg[f * HW + bm + mm];
            }
            __syncthreads();
        }

        int ci = (k0 + sk) & 255;
        const float* p = imgb + ((size_t)ci << 12);
        if (MODE == 0) {
            int dy = tap / 3 - 1, dx = tap % 3 - 1;
#pragma unroll
            for (int s = 0; s < SREP; s++) {
                int m = sm + s * MQ;
                int y = ((bm + m) >> 6) + dy;
                int x = (m & 63) + dx;
                float v = 0.f;
                if ((unsigned)y < 64u && (unsigned)x < 64u)
                    v = __ldg(p + (y << 6) + x);
                As[sk * 128 + (m ^ ((sk & 3) << 3))] = f2tf32(v);
            }
        } else {
#pragma unroll
            for (int s = 0; s < SREP; s++) {
                int m = sm + s * MQ;
                int i00 = Ms[m],       i01 = Ms[128 + m];
                int i10 = Ms[256 + m], i11 = Ms[384 + m];
                float w00 = __uint_as_float(Ms[512 + m]);
                float w01 = __uint_as_float(Ms[640 + m]);
                float w10 = __uint_as_float(Ms[768 + m]);
                float w11 = __uint_as_float(Ms[896 + m]);
                float v = w00 * __ldg(p + i00) + w01 * __ldg(p + i01)
                        + w10 * __ldg(p + i10) + w11 * __ldg(p + i11);
                As[sk * 128 + (m ^ ((sk & 3) << 3))] = f2tf32(v);
            }
        }

        // stage B (pre-converted tf32), 4 uint4 per thread
#pragma unroll
        for (int s = 0; s < 4; s++) {
            int vx = tid + s * NT;                 // 0..4*BN-1
            int k = vx / (BN / 4), nq = vx % (BN / 4);
            uint4 b4 = *(const uint4*)(Bw + (size_t)(k0 + k) * ldb + nq * 4);
            *(uint4*)&Bs[k * BN + ((nq * 4) ^ ((k & 3) << 3))] = b4;
        }
        __syncthreads();

#pragma unroll
        for (int ks = 0; ks < BKT; ks += 8) {
            uint32_t bf[8][2];
#pragma unroll
            for (int nt = 0; nt < 8; nt++) {
                int n0 = wn + nt * 8 + r;
                bf[nt][0] = Bs[(ks + c) * BN + (n0 ^ (c << 3))];
                bf[nt][1] = Bs[(ks + c + 4) * BN + (n0 ^ (c << 3))];
            }
#pragma unroll
            for (int mt = 0; mt < 4; mt++) {
                int m0 = wm + mt * 16 + r;
                uint32_t a0 = As[(ks + c) * 128 + (m0 ^ (c << 3))];
                uint32_t a1 = As[(ks + c) * 128 + ((m0 + 8) ^ (c << 3))];
                uint32_t a2 = As[(ks + c + 4) * 128 + (m0 ^ (c << 3))];
                uint32_t a3 = As[(ks + c + 4) * 128 + ((m0 + 8) ^ (c << 3))];
#pragma unroll
                for (int nt = 0; nt < 8; nt++)
                    mma_tf32(acc[mt][nt], a0, a1, a2, a3, bf[nt][0], bf[nt][1]);
            }
        }
        __syncthreads();
    }

    // epilogue: c0:(r,2c) c1:(r,2c+1) c2:(r+8,2c) c3:(r+8,2c+1)
    float* Cb = Cout + (size_t)b * cBatch;
#pragma unroll
    for (int mt = 0; mt < 4; mt++) {
        int m = bm + wm + mt * 16 + r;
#pragma unroll
        for (int nt = 0; nt < 8; nt++) {
            int n = wn + nt * 8 + 2 * c;
            if (n < Nreal) {
                float bv = bias ? bias[n] : 0.f;
                Cb[(size_t)n * HW + m]     = acc[mt][nt][0] + bv;
                Cb[(size_t)n * HW + m + 8] = acc[mt][nt][2] + bv;
            }
            if (n + 1 < Nreal) {
                float bv = bias ? bias[n + 1] : 0.f;
                Cb[(size_t)(n + 1) * HW + m]     = acc[mt][nt][1] + bv;
                Cb[(size_t)(n + 1) * HW + m + 8] = acc[mt][nt][3] + bv;
            }
        }
    }
}

// ---------------- launch ----------------------------------------------------
extern "C" void kernel_launch(void* const* d_in, const int* in_sizes, int n_in,
                              void* d_out, int out_size) {
    const float* cls_feat = (const float*)d_in[0];
    const float* reg_feat = (const float*)d_in[1];
    const float* offc_w   = (const float*)d_in[2];
    const float* offc_b   = (const float*)d_in[3];
    const float* offc_g   = (const float*)d_in[4];
    const float* offc_bt  = (const float*)d_in[5];
    const float* offo_w   = (const float*)d_in[6];
    const float* offo_b   = (const float*)d_in[7];
    const float* clsdc_w  = (const float*)d_in[8];
    const float* cls_g    = (const float*)d_in[9];
    const float* cls_bt   = (const float*)d_in[10];
    const float* regdc_w  = (const float*)d_in[11];
    const float* reg_g    = (const float*)d_in[12];
    const float* reg_bt   = (const float*)d_in[13];

    float* out = (float*)d_out;
    float* pts = out;                          // [4][18][4096]
    float* cls_out = out + (size_t)BB * 18 * HW;
    float* reg_out = cls_out + (size_t)BB * CC * HW;

    float *t, *raw;
    uint32_t *wT1, *wT2, *wTc, *wTr, *meta;
    cudaGetSymbolAddress((void**)&t, g_t);
    cudaGetSymbolAddress((void**)&raw, g_raw);
    cudaGetSymbolAddress((void**)&wT1, g_wT1);
    cudaGetSymbolAddress((void**)&wT2, g_wT2);
    cudaGetSymbolAddress((void**)&wTc, g_wTc);
    cudaGetSymbolAddress((void**)&wTr, g_wTr);
    cudaGetSymbolAddress((void**)&meta, g_meta);

    transpose_w_tf32<<<(KK * 256 + 255) / 256, 256>>>(offc_w, wT1, 256, 256);
    transpose_w_tf32<<<(KK * 128 + 255) / 256, 256>>>(offo_w, wT2, 18, 128);
    transpose_w_tf32<<<(KK * 256 + 255) / 256, 256>>>(clsdc_w, wTc, 256, 256);
    transpose_w_tf32<<<(KK * 256 + 255) / 256, 256>>>(regdc_w, wTr, 256, 256);

    const dim3 gBig(32, 1, 4);
    const int gnApplyBlocks = (BB * CC * HW) / 256;

    // ---- offset branch: conv1 -> GN -> ReLU -> conv2 -> pts ----
    fgemm<0, 256><<<gBig, 256>>>(reg_feat, wT1, nullptr, raw, offc_b, 256, 256, (long)CC * HW);
    gn_stats<<<BB * NG, 256>>>(raw);
    gn_apply<<<gnApplyBlocks, 256>>>(raw, offc_g, offc_bt, t);
    fgemm<0, 128><<<gBig, 128>>>(t, wT2, nullptr, pts, offo_b, 18, 128, 18L * HW);

    // ---- bilinear meta from pts ----
    deform_meta<<<dim3(16, K9, BB), 256>>>(pts, meta);

    // ---- cls branch ----
    fgemm<1, 256><<<gBig, 256>>>(cls_feat, wTc, meta, raw, nullptr, 256, 256, (long)CC * HW);
    gn_stats<<<BB * NG, 256>>>(raw);
    gn_apply<<<gnApplyBlocks, 256>>>(raw, cls_g, cls_bt, cls_out);

    // ---- reg branch ----
    fgemm<1, 256><<<gBig, 256>>>(reg_feat, wTr, meta, raw, nullptr, 256, 256, (long)CC * HW);
    gn_stats<<<BB * NG, 256>>>(raw);
    gn_apply<<<gnApplyBlocks, 256>>>(raw, reg_g, reg_bt, reg_out);
}

// round 5
// speedup vs baseline: 1.5380x; 1.5380x over previous
#include <cuda_runtime.h>
#include <math.h>
#include <stdint.h>

#define BB 4
#define CC 256
#define HW 4096
#define K9 9
#define KK 2304   // 256*9
#define NG 32
#define CPG 8
#define NCHB 144  // KK/16 k-blocks

// ---------------- static scratch ----------------
__device__ uint32_t g_cols[(size_t)BB * KK * HW];  // tf32 bits, [b][kk][m]
__device__ float g_raw[BB * CC * HW];
__device__ uint32_t g_wT1[KK * 256];               // tf32 bits, [kk][o]
__device__ uint32_t g_wT2[KK * 32];
__device__ uint32_t g_wTc[KK * 256];
__device__ uint32_t g_wTr[KK * 256];
__device__ float g_mu[BB * NG];
__device__ float g_rstd[BB * NG];

// ---------------- helpers ----------------
__device__ __forceinline__ uint32_t f2tf32(float x) {
    uint32_t r;
    asm("cvt.rna.tf32.f32 %0, %1;" : "=r"(r) : "f"(x));
    return r;
}

__device__ __forceinline__ uint32_t smem_u32(const void* p) {
    uint32_t a;
    asm("{ .reg .u64 t; cvta.to.shared.u64 t, %1; cvt.u32.u64 %0, t; }"
        : "=r"(a) : "l"(p));
    return a;
}

__device__ __forceinline__ void cp16(uint32_t dst, const void* src) {
    asm volatile("cp.async.cg.shared.global [%0], [%1], 16;"
                 :: "r"(dst), "l"(src) : "memory");
}
__device__ __forceinline__ void cp_commit() {
    asm volatile("cp.async.commit_group;" ::: "memory");
}
__device__ __forceinline__ void cp_wait1() {
    asm volatile("cp.async.wait_group 1;" ::: "memory");
}
__device__ __forceinline__ void cp_wait0() {
    asm volatile("cp.async.wait_group 0;" ::: "memory");
}

__device__ __forceinline__ void mma_tf32(float* d, uint32_t a0, uint32_t a1,
                                         uint32_t a2, uint32_t a3,
                                         uint32_t b0, uint32_t b1) {
    asm volatile(
        "mma.sync.aligned.m16n8k8.row.col.f32.tf32.tf32.f32 "
        "{%0,%1,%2,%3}, {%4,%5,%6,%7}, {%8,%9}, {%0,%1,%2,%3};"
        : "+f"(d[0]), "+f"(d[1]), "+f"(d[2]), "+f"(d[3])
        : "r"(a0), "r"(a1), "r"(a2), "r"(a3), "r"(b0), "r"(b1));
}

// ---------------- weight transpose -> tf32: wT[(tap*256+ci)][o] ------------
__global__ void transpose_w_tf32(const float* __restrict__ w, uint32_t* __restrict__ wT,
                                 int O, int ldo) {
    int i = blockIdx.x * 256 + threadIdx.x;
    if (i >= KK * ldo) return;
    int o = i % ldo;
    int kk = i / ldo;
    int ci = kk % CC;
    int tap = kk / CC;
    float v = (o < O) ? w[(o * CC + ci) * K9 + tap] : 0.f;
    wT[i] = f2tf32(v);
}

// ---------------- im2col 3x3 pad1 -> tf32 cols[b][tap*256+ci][m] ------------
__global__ void im2col_tf32(const float* __restrict__ in, uint32_t* __restrict__ cols) {
    int i = blockIdx.x * 256 + threadIdx.x;
    int m = i & (HW - 1);
    int r = i >> 12;
    int kk = r % KK;
    int b = r / KK;
    int ci = kk % CC;
    int tap = kk / CC;
    int y = (m >> 6) + (tap / 3) - 1;
    int x = (m & 63) + (tap % 3) - 1;
    float v = 0.f;
    if ((unsigned)y < 64u && (unsigned)x < 64u)
        v = in[((b * CC + ci) * 64 + y) * 64 + x];
    cols[i] = f2tf32(v);
}

// ---------------- im2col fused with GN+ReLU (conv2 input) ------------------
__global__ void im2col_gn_tf32(const float* __restrict__ raw,
                               const float* __restrict__ gamma,
                               const float* __restrict__ beta,
                               uint32_t* __restrict__ cols) {
    int i = blockIdx.x * 256 + threadIdx.x;
    int m = i & (HW - 1);
    int r = i >> 12;
    int kk = r % KK;
    int b = r / KK;
    int ci = kk % CC;
    int tap = kk / CC;
    int y = (m >> 6) + (tap / 3) - 1;
    int x = (m & 63) + (tap % 3) - 1;
    float v = 0.f;
    if ((unsigned)y < 64u && (unsigned)x < 64u) {
        int bg = b * NG + (ci >> 3);
        float t = raw[((b * CC + ci) * 64 + y) * 64 + x];
        v = fmaxf((t - g_mu[bg]) * g_rstd[bg] * gamma[ci] + beta[ci], 0.f);
    }
    cols[i] = f2tf32(v);
}

// ---------------- deformable sampling -> tf32 cols[b][k*256+c][m] ----------
__global__ void deform_cols_tf32(const float* __restrict__ img,
                                 const float* __restrict__ pts,
                                 uint32_t* __restrict__ cols) {
    int m = blockIdx.x * 256 + threadIdx.x;
    int k = blockIdx.y, b = blockIdx.z;
    int y = m >> 6, x = m & 63;
    float pty = pts[(b * 18 + 2 * k) * HW + m];
    float ptx = pts[(b * 18 + 2 * k + 1) * HW + m];
    float bx = (float)(k - 4);
    float py = pty + (float)y;
    float px = ((ptx - bx) + (float)x) + bx;
    float y0f = floorf(py), x0f = floorf(px);
    int y0 = (int)y0f, x0 = (int)x0f;
    float wy = py - y0f, wx = px - x0f;
    float w00 = (1.f - wy) * (1.f - wx);
    float w01 = (1.f - wy) * wx;
    float w10 = wy * (1.f - wx);
    float w11 = wy * wx;
    bool vy0 = (y0 >= 0) && (y0 <= 63);
    bool vy1 = (y0 + 1 >= 0) && (y0 + 1 <= 63);
    bool vx0 = (x0 >= 0) && (x0 <= 63);
    bool vx1 = (x0 + 1 >= 0) && (x0 + 1 <= 63);
    w00 = (vy0 && vx0) ? w00 : 0.f;
    w01 = (vy0 && vx1) ? w01 : 0.f;
    w10 = (vy1 && vx0) ? w10 : 0.f;
    w11 = (vy1 && vx1) ? w11 : 0.f;
    int y0c = min(max(y0, 0), 63), y1c = min(max(y0 + 1, 0), 63);
    int x0c = min(max(x0, 0), 63), x1c = min(max(x0 + 1, 0), 63);
    int i00 = y0c * 64 + x0c, i01 = y0c * 64 + x1c;
    int i10 = y1c * 64 + x0c, i11 = y1c * 64 + x1c;
    const float* ib = img + (size_t)b * CC * HW;
    uint32_t* cb = cols + ((size_t)b * KK + (size_t)k * CC) * HW + m;
#pragma unroll 4
    for (int c = 0; c < CC; c++) {
        const float* ic = ib + (size_t)c * HW;
        float v = w00 * __ldg(ic + i00) + w01 * __ldg(ic + i01)
                + w10 * __ldg(ic + i10) + w11 * __ldg(ic + i11);
        cb[(size_t)c * HW] = f2tf32(v);
    }
}

// ---------------- GroupNorm ----------------
__global__ void gn_stats(const float* __restrict__ raw) {
    int bg = blockIdx.x;
    const float* p = raw + (size_t)bg * CPG * HW;
    float s = 0.f, ss = 0.f;
    for (int i = threadIdx.x; i < CPG * HW; i += 256) {
        float v = p[i];
        s += v; ss += v * v;
    }
    __shared__ float sh[512];
    sh[threadIdx.x] = s;
    sh[256 + threadIdx.x] = ss;
    __syncthreads();
    for (int o = 128; o > 0; o >>= 1) {
        if (threadIdx.x < o) {
            sh[threadIdx.x] += sh[threadIdx.x + o];
            sh[256 + threadIdx.x] += sh[256 + threadIdx.x + o];
        }
        __syncthreads();
    }
    if (threadIdx.x == 0) {
        const float inv_n = 1.f / (float)(CPG * HW);
        float mean = sh[0] * inv_n;
        float var = sh[256] * inv_n - mean * mean;
        g_mu[bg] = mean;
        g_rstd[bg] = rsqrtf(var + 1e-5f);
    }
}

__global__ void gn_apply(const float* __restrict__ raw,
                         const float* __restrict__ gamma,
                         const float* __restrict__ beta,
                         float* __restrict__ out) {
    int i = blockIdx.x * 256 + threadIdx.x;
    int c = (i >> 12) & 255;
    int bg = i >> 15;
    float v = (raw[i] - g_mu[bg]) * g_rstd[bg] * gamma[c] + beta[c];
    out[i] = fmaxf(v, 0.f);
}

// ---------------- TF32 mma.sync GEMM with cp.async double buffering --------
// C[b][n][m] = sum_kk A[b][kk][m] * Bw[kk][n]. A,Bw pre-converted tf32 bits.
// BM=128, BN=16*WN, BK=16. 4 warps: 2 in m (64 rows each) x 2 in n (8*WN each).
template<int WN>
__global__ void __launch_bounds__(128, 2)
tgemm(const uint32_t* __restrict__ A, const uint32_t* __restrict__ Bw,
      float* __restrict__ Cout, const float* __restrict__ bias,
      int Nreal, int ldb, long cBatch) {
    constexpr int BN = 16 * WN;
    __shared__ uint32_t As[2][16 * 128];
    __shared__ uint32_t Bs[2][16 * BN];

    int bm = blockIdx.x * 128, bn = blockIdx.y * BN, b = blockIdx.z;
    const uint32_t* Ab = A + (size_t)b * KK * HW + bm;
    const uint32_t* Bb = Bw + bn;
    int tid = threadIdx.x;
    int warp = tid >> 5, lane = tid & 31;
    int wm = (warp & 1) * 64, wn = (warp >> 1) * (8 * WN);
    int r = lane >> 2, c = lane & 3;

    float acc[4][WN][4];
#pragma unroll
    for (int mt = 0; mt < 4; mt++)
#pragma unroll
        for (int nt = 0; nt < WN; nt++)
#pragma unroll
            for (int i = 0; i < 4; i++) acc[mt][nt][i] = 0.f;

    auto stage = [&](int k0, int buf) {
#pragma unroll
        for (int s = 0; s < 4; s++) {
            int idx = tid + s * 128;
            int k = idx >> 5, mq = idx & 31;
            cp16(smem_u32(&As[buf][k * 128 + ((mq * 4) ^ ((k & 3) << 3))]),
                 Ab + (size_t)(k0 + k) * HW + mq * 4);
        }
        constexpr int BQ = BN / 4;
#pragma unroll
        for (int s = 0; s < (16 * BQ) / 128; s++) {
            int idx = tid + s * 128;
            int k = idx / BQ, nq = idx % BQ;
            cp16(smem_u32(&Bs[buf][k * BN + ((nq * 4) ^ ((k & 3) << 3))]),
                 Bb + (size_t)(k0 + k) * ldb + nq * 4);
        }
    };

    stage(0, 0);
    cp_commit();

    for (int cc = 0; cc < NCHB; cc++) {
        int buf = cc & 1;
        if (cc + 1 < NCHB) {
            stage((cc + 1) * 16, buf ^ 1);
            cp_commit();
            cp_wait1();
        } else {
            cp_wait0();
        }
        __syncthreads();
#pragma unroll
        for (int ks = 0; ks < 16; ks += 8) {
            uint32_t bf[WN][2];
#pragma unroll
            for (int nt = 0; nt < WN; nt++) {
                int n0 = wn + nt * 8 + r;
                bf[nt][0] = Bs[buf][(ks + c) * BN + (n0 ^ (c << 3))];
                bf[nt][1] = Bs[buf][(ks + c + 4) * BN + (n0 ^ (c << 3))];
            }
#pragma unroll
            for (int mt = 0; mt < 4; mt++) {
                int m0 = wm + mt * 16 + r;
                uint32_t a0 = As[buf][(ks + c) * 128 + (m0 ^ (c << 3))];
                uint32_t a1 = As[buf][(ks + c) * 128 + ((m0 + 8) ^ (c << 3))];
                uint32_t a2 = As[buf][(ks + c + 4) * 128 + (m0 ^ (c << 3))];
                uint32_t a3 = As[buf][(ks + c + 4) * 128 + ((m0 + 8) ^ (c << 3))];
#pragma unroll
                for (int nt = 0; nt < WN; nt++)
                    mma_tf32(acc[mt][nt], a0, a1, a2, a3, bf[nt][0], bf[nt][1]);
            }
        }
        __syncthreads();
    }

    // epilogue: c0:(r,2c) c1:(r,2c+1) c2:(r+8,2c) c3:(r+8,2c+1)
    float* Cb = Cout + (size_t)b * cBatch;
#pragma unroll
    for (int mt = 0; mt < 4; mt++) {
        int m = bm + wm + mt * 16 + r;
#pragma unroll
        for (int nt = 0; nt < WN; nt++) {
            int n = bn + wn + nt * 8 + 2 * c;
            if (n < Nreal) {
                float bv = bias ? bias[n] : 0.f;
                Cb[(size_t)n * HW + m]     = acc[mt][nt][0] + bv;
                Cb[(size_t)n * HW + m + 8] = acc[mt][nt][2] + bv;
            }
            if (n + 1 < Nreal) {
                float bv = bias ? bias[n + 1] : 0.f;
                Cb[(size_t)(n + 1) * HW + m]     = acc[mt][nt][1] + bv;
                Cb[(size_t)(n + 1) * HW + m + 8] = acc[mt][nt][3] + bv;
            }
        }
    }
}

// ---------------- launch ----------------------------------------------------
extern "C" void kernel_launch(void* const* d_in, const int* in_sizes, int n_in,
                              void* d_out, int out_size) {
    const float* cls_feat = (const float*)d_in[0];
    const float* reg_feat = (const float*)d_in[1];
    const float* offc_w   = (const float*)d_in[2];
    const float* offc_b   = (const float*)d_in[3];
    const float* offc_g   = (const float*)d_in[4];
    const float* offc_bt  = (const float*)d_in[5];
    const float* offo_w   = (const float*)d_in[6];
    const float* offo_b   = (const float*)d_in[7];
    const float* clsdc_w  = (const float*)d_in[8];
    const float* cls_g    = (const float*)d_in[9];
    const float* cls_bt   = (const float*)d_in[10];
    const float* regdc_w  = (const float*)d_in[11];
    const float* reg_g    = (const float*)d_in[12];
    const float* reg_bt   = (const float*)d_in[13];

    float* out = (float*)d_out;
    float* pts = out;                          // [4][18][4096]
    float* cls_out = out + (size_t)BB * 18 * HW;
    float* reg_out = cls_out + (size_t)BB * CC * HW;

    float* raw;
    uint32_t *cols, *wT1, *wT2, *wTc, *wTr;
    cudaGetSymbolAddress((void**)&cols, g_cols);
    cudaGetSymbolAddress((void**)&raw, g_raw);
    cudaGetSymbolAddress((void**)&wT1, g_wT1);
    cudaGetSymbolAddress((void**)&wT2, g_wT2);
    cudaGetSymbolAddress((void**)&wTc, g_wTc);
    cudaGetSymbolAddress((void**)&wTr, g_wTr);

    transpose_w_tf32<<<(KK * 256) / 256, 256>>>(offc_w, wT1, 256, 256);
    transpose_w_tf32<<<(KK * 32 + 255) / 256, 256>>>(offo_w, wT2, 18, 32);
    transpose_w_tf32<<<(KK * 256) / 256, 256>>>(clsdc_w, wTc, 256, 256);
    transpose_w_tf32<<<(KK * 256) / 256, 256>>>(regdc_w, wTr, 256, 256);

    const int colsBlocks = (BB * KK * HW) / 256;
    const dim3 gBig(32, 2, 4);   // BN=128, N=256
    const dim3 gPts(32, 1, 4);   // BN=32, N=18
    const dim3 gDef(16, K9, BB);
    const int gnApplyBlocks = (BB * CC * HW) / 256;

    // ---- offset branch: conv1 -> GN -> ReLU -> conv2 -> pts ----
    im2col_tf32<<<colsBlocks, 256>>>(reg_feat, cols);
    tgemm<8><<<gBig, 128>>>(cols, wT1, raw, offc_b, 256, 256, (long)CC * HW);
    gn_stats<<<BB * NG, 256>>>(raw);
    im2col_gn_tf32<<<colsBlocks, 256>>>(raw, offc_g, offc_bt, cols);
    tgemm<2><<<gPts, 128>>>(cols, wT2, pts, offo_b, 18, 32, 18L * HW);

    // ---- cls branch ----
    deform_cols_tf32<<<gDef, 256>>>(cls_feat, pts, cols);
    tgemm<8><<<gBig, 128>>>(cols, wTc, raw, nullptr, 256, 256, (long)CC * HW);
    gn_stats<<<BB * NG, 256>>>(raw);
    gn_apply<<<gnApplyBlocks, 256>>>(raw, cls_g, cls_bt, cls_out);

    // ---- reg branch ----
    deform_cols_tf32<<<gDef, 256>>>(reg_feat, pts, cols);
    tgemm<8><<<gBig, 128>>>(cols, wTr, raw, nullptr, 256, 256, (long)CC * HW);
    gn_stats<<<BB * NG, 256>>>(raw);
    gn_apply<<<gnApplyBlocks, 256>>>(raw, reg_g, reg_bt, reg_out);
}

// round 6
// speedup vs baseline: 1.6097x; 1.0467x over previous
#include <cuda_runtime.h>
#include <math.h>
#include <stdint.h>

#define BB 4
#define CC 256
#define HW 4096
#define K9 9
#define KK 2304   // 256*9
#define NG 32
#define CPG 8
#define NCHB 144  // KK/16 k-blocks

// ---------------- static scratch ----------------
__device__ uint32_t g_cols[(size_t)BB * KK * HW];   // tf32 bits, [b][kk][m]
__device__ uint32_t g_cols2[(size_t)BB * KK * HW];  // second buffer (reg branch)
__device__ float g_raw[BB * CC * HW];
__device__ float g_raw2[BB * CC * HW];
__device__ uint32_t g_wT1[KK * 256];                // tf32 bits, [kk][o]
__device__ uint32_t g_wT2[KK * 32];
__device__ uint32_t g_wTc[KK * 256];
__device__ uint32_t g_wTr[KK * 256];
__device__ float g_mu[3 * BB * NG];                 // slot 0: conv1, 1: cls, 2: reg
__device__ float g_rstd[3 * BB * NG];

// ---------------- streams / events (host-side, created before checkpoints) --
struct StreamHolder {
    cudaStream_t s1, s2;
    cudaEvent_t eF, eT, eP, eR;
    StreamHolder() {
        if (cudaStreamCreateWithFlags(&s1, cudaStreamNonBlocking) != cudaSuccess) s1 = 0;
        if (cudaStreamCreateWithFlags(&s2, cudaStreamNonBlocking) != cudaSuccess) s2 = 0;
        cudaEventCreateWithFlags(&eF, cudaEventDisableTiming);
        cudaEventCreateWithFlags(&eT, cudaEventDisableTiming);
        cudaEventCreateWithFlags(&eP, cudaEventDisableTiming);
        cudaEventCreateWithFlags(&eR, cudaEventDisableTiming);
    }
};
static StreamHolder g_sh;

// ---------------- helpers ----------------
__device__ __forceinline__ uint32_t f2tf32(float x) {
    uint32_t r;
    asm("cvt.rna.tf32.f32 %0, %1;" : "=r"(r) : "f"(x));
    return r;
}

__device__ __forceinline__ uint32_t smem_u32(const void* p) {
    uint32_t a;
    asm("{ .reg .u64 t; cvta.to.shared.u64 t, %1; cvt.u32.u64 %0, t; }"
        : "=r"(a) : "l"(p));
    return a;
}

__device__ __forceinline__ void cp16(uint32_t dst, const void* src) {
    asm volatile("cp.async.cg.shared.global [%0], [%1], 16;"
                 :: "r"(dst), "l"(src) : "memory");
}
__device__ __forceinline__ void cp_commit() {
    asm volatile("cp.async.commit_group;" ::: "memory");
}
__device__ __forceinline__ void cp_wait2() {
    asm volatile("cp.async.wait_group 2;" ::: "memory");
}

__device__ __forceinline__ void mma_tf32(float* d, uint32_t a0, uint32_t a1,
                                         uint32_t a2, uint32_t a3,
                                         uint32_t b0, uint32_t b1) {
    asm volatile(
        "mma.sync.aligned.m16n8k8.row.col.f32.tf32.tf32.f32 "
        "{%0,%1,%2,%3}, {%4,%5,%6,%7}, {%8,%9}, {%0,%1,%2,%3};"
        : "+f"(d[0]), "+f"(d[1]), "+f"(d[2]), "+f"(d[3])
        : "r"(a0), "r"(a1), "r"(a2), "r"(a3), "r"(b0), "r"(b1));
}

// ---------------- fused weight transpose -> tf32 ---------------------------
// Handles all 4 weight tensors in one launch.
__global__ void transpose_all(const float* __restrict__ w1, const float* __restrict__ w2,
                              const float* __restrict__ wc, const float* __restrict__ wr,
                              uint32_t* __restrict__ o1, uint32_t* __restrict__ o2,
                              uint32_t* __restrict__ oc, uint32_t* __restrict__ orr) {
    const int S = KK * 256;
    int i = blockIdx.x * 256 + threadIdx.x;
    const float* w; uint32_t* o; int O, ldo, j;
    if (i < S)            { w = w1; o = o1;  O = 256; ldo = 256; j = i; }
    else if (i < 2 * S)   { w = wc; o = oc;  O = 256; ldo = 256; j = i - S; }
    else if (i < 3 * S)   { w = wr; o = orr; O = 256; ldo = 256; j = i - 2 * S; }
    else {
        j = i - 3 * S;
        if (j >= KK * 32) return;
        w = w2; o = o2; O = 18; ldo = 32;
    }
    int oo = j % ldo;
    int kk = j / ldo;
    int ci = kk % CC;
    int tap = kk / CC;
    float v = (oo < O) ? w[(oo * CC + ci) * K9 + tap] : 0.f;
    o[j] = f2tf32(v);
}

// ---------------- im2col 3x3 pad1 -> tf32 cols[b][tap*256+ci][m] ------------
__global__ void im2col_tf32(const float* __restrict__ in, uint32_t* __restrict__ cols) {
    int i = blockIdx.x * 256 + threadIdx.x;
    int m = i & (HW - 1);
    int r = i >> 12;
    int kk = r % KK;
    int b = r / KK;
    int ci = kk % CC;
    int tap = kk / CC;
    int y = (m >> 6) + (tap / 3) - 1;
    int x = (m & 63) + (tap % 3) - 1;
    float v = 0.f;
    if ((unsigned)y < 64u && (unsigned)x < 64u)
        v = in[((b * CC + ci) * 64 + y) * 64 + x];
    cols[i] = f2tf32(v);
}

// ---------------- im2col fused with GN+ReLU (conv2 input) ------------------
__global__ void im2col_gn_tf32(const float* __restrict__ raw,
                               const float* __restrict__ gamma,
                               const float* __restrict__ beta,
                               const float* __restrict__ mu,
                               const float* __restrict__ rstd,
                               uint32_t* __restrict__ cols) {
    int i = blockIdx.x * 256 + threadIdx.x;
    int m = i & (HW - 1);
    int r = i >> 12;
    int kk = r % KK;
    int b = r / KK;
    int ci = kk % CC;
    int tap = kk / CC;
    int y = (m >> 6) + (tap / 3) - 1;
    int x = (m & 63) + (tap % 3) - 1;
    float v = 0.f;
    if ((unsigned)y < 64u && (unsigned)x < 64u) {
        int bg = b * NG + (ci >> 3);
        float t = raw[((b * CC + ci) * 64 + y) * 64 + x];
        v = fmaxf((t - mu[bg]) * rstd[bg] * gamma[ci] + beta[ci], 0.f);
    }
    cols[i] = f2tf32(v);
}

// ---------------- deformable sampling -> tf32 cols[b][k*256+c][m] ----------
__global__ void deform_cols_tf32(const float* __restrict__ img,
                                 const float* __restrict__ pts,
                                 uint32_t* __restrict__ cols) {
    int m = blockIdx.x * 256 + threadIdx.x;
    int k = blockIdx.y, b = blockIdx.z;
    int y = m >> 6, x = m & 63;
    float pty = pts[(b * 18 + 2 * k) * HW + m];
    float ptx = pts[(b * 18 + 2 * k + 1) * HW + m];
    float bx = (float)(k - 4);
    float py = pty + (float)y;
    float px = ((ptx - bx) + (float)x) + bx;
    float y0f = floorf(py), x0f = floorf(px);
    int y0 = (int)y0f, x0 = (int)x0f;
    float wy = py - y0f, wx = px - x0f;
    float w00 = (1.f - wy) * (1.f - wx);
    float w01 = (1.f - wy) * wx;
    float w10 = wy * (1.f - wx);
    float w11 = wy * wx;
    bool vy0 = (y0 >= 0) && (y0 <= 63);
    bool vy1 = (y0 + 1 >= 0) && (y0 + 1 <= 63);
    bool vx0 = (x0 >= 0) && (x0 <= 63);
    bool vx1 = (x0 + 1 >= 0) && (x0 + 1 <= 63);
    w00 = (vy0 && vx0) ? w00 : 0.f;
    w01 = (vy0 && vx1) ? w01 : 0.f;
    w10 = (vy1 && vx0) ? w10 : 0.f;
    w11 = (vy1 && vx1) ? w11 : 0.f;
    int y0c = min(max(y0, 0), 63), y1c = min(max(y0 + 1, 0), 63);
    int x0c = min(max(x0, 0), 63), x1c = min(max(x0 + 1, 0), 63);
    int i00 = y0c * 64 + x0c, i01 = y0c * 64 + x1c;
    int i10 = y1c * 64 + x0c, i11 = y1c * 64 + x1c;
    const float* ib = img + (size_t)b * CC * HW;
    uint32_t* cb = cols + ((size_t)b * KK + (size_t)k * CC) * HW + m;
#pragma unroll 4
    for (int c = 0; c < CC; c++) {
        const float* ic = ib + (size_t)c * HW;
        float v = w00 * __ldg(ic + i00) + w01 * __ldg(ic + i01)
                + w10 * __ldg(ic + i10) + w11 * __ldg(ic + i11);
        cb[(size_t)c * HW] = f2tf32(v);
    }
}

// ---------------- GroupNorm ----------------
__global__ void gn_stats(const float* __restrict__ raw, float* __restrict__ mu,
                         float* __restrict__ rstd) {
    int bg = blockIdx.x;
    const float* p = raw + (size_t)bg * CPG * HW;
    float s = 0.f, ss = 0.f;
    for (int i = threadIdx.x; i < CPG * HW; i += 256) {
        float v = p[i];
        s += v; ss += v * v;
    }
    __shared__ float sh[512];
    sh[threadIdx.x] = s;
    sh[256 + threadIdx.x] = ss;
    __syncthreads();
    for (int o = 128; o > 0; o >>= 1) {
        if (threadIdx.x < o) {
            sh[threadIdx.x] += sh[threadIdx.x + o];
            sh[256 + threadIdx.x] += sh[256 + threadIdx.x + o];
        }
        __syncthreads();
    }
    if (threadIdx.x == 0) {
        const float inv_n = 1.f / (float)(CPG * HW);
        float mean = sh[0] * inv_n;
        float var = sh[256] * inv_n - mean * mean;
        mu[bg] = mean;
        rstd[bg] = rsqrtf(var + 1e-5f);
    }
}

__global__ void gn_apply(const float* __restrict__ raw,
                         const float* __restrict__ gamma,
                         const float* __restrict__ beta,
                         const float* __restrict__ mu,
                         const float* __restrict__ rstd,
                         float* __restrict__ out) {
    int i = blockIdx.x * 256 + threadIdx.x;
    int c = (i >> 12) & 255;
    int bg = i >> 15;
    float v = (raw[i] - mu[bg]) * rstd[bg] * gamma[c] + beta[c];
    out[i] = fmaxf(v, 0.f);
}

// ---------------- TF32 mma.sync GEMM, 3-stage cp.async pipeline ------------
// C[b][n][m] = sum_kk A[b][kk][m] * Bw[kk][n]. A,Bw pre-converted tf32 bits.
// BM=128, BN=16*WN, BK=16. 4 warps: 2 in m (64 rows) x 2 in n (8*WN cols).
template<int WN>
__global__ void __launch_bounds__(128, 2)
tgemm(const uint32_t* __restrict__ A, const uint32_t* __restrict__ Bw,
      float* __restrict__ Cout, const float* __restrict__ bias,
      int Nreal, int ldb, long cBatch) {
    constexpr int BN = 16 * WN;
    __shared__ uint32_t As[3][16 * 128];
    __shared__ uint32_t Bs[3][16 * BN];

    int bm = blockIdx.x * 128, bn = blockIdx.y * BN, b = blockIdx.z;
    const uint32_t* Ab = A + (size_t)b * KK * HW + bm;
    const uint32_t* Bb = Bw + bn;
    int tid = threadIdx.x;
    int warp = tid >> 5, lane = tid & 31;
    int wm = (warp & 1) * 64, wn = (warp >> 1) * (8 * WN);
    int r = lane >> 2, c = lane & 3;

    float acc[4][WN][4];
#pragma unroll
    for (int mt = 0; mt < 4; mt++)
#pragma unroll
        for (int nt = 0; nt < WN; nt++)
#pragma unroll
            for (int i = 0; i < 4; i++) acc[mt][nt][i] = 0.f;

    auto stage = [&](int k0, int buf) {
#pragma unroll
        for (int s = 0; s < 4; s++) {
            int idx = tid + s * 128;
            int k = idx >> 5, mq = idx & 31;
            cp16(smem_u32(&As[buf][k * 128 + ((mq * 4) ^ ((k & 3) << 3))]),
                 Ab + (size_t)(k0 + k) * HW + mq * 4);
        }
        constexpr int BQ = BN / 4;
#pragma unroll
        for (int s = 0; s < (16 * BQ) / 128; s++) {
            int idx = tid + s * 128;
            int k = idx / BQ, nq = idx % BQ;
            cp16(smem_u32(&Bs[buf][k * BN + ((nq * 4) ^ ((k & 3) << 3))]),
                 Bb + (size_t)(k0 + k) * ldb + nq * 4);
        }
    };

    stage(0, 0); cp_commit();
    stage(16, 1); cp_commit();

    int buf = 0;
    for (int cc = 0; cc < NCHB; cc++) {
        if (cc + 2 < NCHB) stage((cc + 2) * 16, (cc + 2) % 3);
        cp_commit();
        cp_wait2();
        __syncthreads();
#pragma unroll
        for (int ks = 0; ks < 16; ks += 8) {
            uint32_t bf[WN][2];
#pragma unroll
            for (int nt = 0; nt < WN; nt++) {
                int n0 = wn + nt * 8 + r;
                bf[nt][0] = Bs[buf][(ks + c) * BN + (n0 ^ (c << 3))];
                bf[nt][1] = Bs[buf][(ks + c + 4) * BN + (n0 ^ (c << 3))];
            }
#pragma unroll
            for (int mt = 0; mt < 4; mt++) {
                int m0 = wm + mt * 16 + r;
                uint32_t a0 = As[buf][(ks + c) * 128 + (m0 ^ (c << 3))];
                uint32_t a1 = As[buf][(ks + c) * 128 + ((m0 + 8) ^ (c << 3))];
                uint32_t a2 = As[buf][(ks + c + 4) * 128 + (m0 ^ (c << 3))];
                uint32_t a3 = As[buf][(ks + c + 4) * 128 + ((m0 + 8) ^ (c << 3))];
#pragma unroll
                for (int nt = 0; nt < WN; nt++)
                    mma_tf32(acc[mt][nt], a0, a1, a2, a3, bf[nt][0], bf[nt][1]);
            }
        }
        __syncthreads();
        buf = (buf == 2) ? 0 : buf + 1;
    }

    // epilogue: c0:(r,2c) c1:(r,2c+1) c2:(r+8,2c) c3:(r+8,2c+1)
    float* Cb = Cout + (size_t)b * cBatch;
#pragma unroll
    for (int mt = 0; mt < 4; mt++) {
        int m = bm + wm + mt * 16 + r;
#pragma unroll
        for (int nt = 0; nt < WN; nt++) {
            int n = bn + wn + nt * 8 + 2 * c;
            if (n < Nreal) {
                float bv = bias ? bias[n] : 0.f;
                Cb[(size_t)n * HW + m]     = acc[mt][nt][0] + bv;
                Cb[(size_t)n * HW + m + 8] = acc[mt][nt][2] + bv;
            }
            if (n + 1 < Nreal) {
                float bv = bias ? bias[n + 1] : 0.f;
                Cb[(size_t)(n + 1) * HW + m]     = acc[mt][nt][1] + bv;
                Cb[(size_t)(n + 1) * HW + m + 8] = acc[mt][nt][3] + bv;
            }
        }
    }
}

// ---------------- launch ----------------------------------------------------
extern "C" void kernel_launch(void* const* d_in, const int* in_sizes, int n_in,
                              void* d_out, int out_size) {
    const float* cls_feat = (const float*)d_in[0];
    const float* reg_feat = (const float*)d_in[1];
    const float* offc_w   = (const float*)d_in[2];
    const float* offc_b   = (const float*)d_in[3];
    const float* offc_g   = (const float*)d_in[4];
    const float* offc_bt  = (const float*)d_in[5];
    const float* offo_w   = (const float*)d_in[6];
    const float* offo_b   = (const float*)d_in[7];
    const float* clsdc_w  = (const float*)d_in[8];
    const float* cls_g    = (const float*)d_in[9];
    const float* cls_bt   = (const float*)d_in[10];
    const float* regdc_w  = (const float*)d_in[11];
    const float* reg_g    = (const float*)d_in[12];
    const float* reg_bt   = (const float*)d_in[13];

    float* out = (float*)d_out;
    float* pts = out;                          // [4][18][4096]
    float* cls_out = out + (size_t)BB * 18 * HW;
    float* reg_out = cls_out + (size_t)BB * CC * HW;

    float *raw, *raw2, *mu, *rstd;
    uint32_t *cols, *cols2, *wT1, *wT2, *wTc, *wTr;
    cudaGetSymbolAddress((void**)&cols, g_cols);
    cudaGetSymbolAddress((void**)&cols2, g_cols2);
    cudaGetSymbolAddress((void**)&raw, g_raw);
    cudaGetSymbolAddress((void**)&raw2, g_raw2);
    cudaGetSymbolAddress((void**)&wT1, g_wT1);
    cudaGetSymbolAddress((void**)&wT2, g_wT2);
    cudaGetSymbolAddress((void**)&wTc, g_wTc);
    cudaGetSymbolAddress((void**)&wTr, g_wTr);
    cudaGetSymbolAddress((void**)&mu, g_mu);
    cudaGetSymbolAddress((void**)&rstd, g_rstd);

    cudaStream_t s1 = g_sh.s1, s2 = g_sh.s2;

    const int colsBlocks = (BB * KK * HW) / 256;
    const int twBlocks = (3 * KK * 256 + KK * 32 + 255) / 256;
    const dim3 gBig(32, 2, 4);   // BN=128, N=256
    const dim3 gPts(32, 1, 4);   // BN=32, N=18
    const dim3 gDef(16, K9, BB);
    const int gnApplyBlocks = (BB * CC * HW) / 256;
    const int NGB = BB * NG;

    // ---- fork: weight transposes on s1 concurrent with first im2col ----
    cudaEventRecord(g_sh.eF, 0);
    cudaStreamWaitEvent(s1, g_sh.eF, 0);
    transpose_all<<<twBlocks, 256, 0, s1>>>(offc_w, offo_w, clsdc_w, regdc_w,
                                            wT1, wT2, wTc, wTr);
    cudaEventRecord(g_sh.eT, s1);

    im2col_tf32<<<colsBlocks, 256>>>(reg_feat, cols);
    cudaStreamWaitEvent(0, g_sh.eT, 0);

    // ---- offset branch: conv1 -> GN -> ReLU -> conv2 -> pts ----
    tgemm<8><<<gBig, 128>>>(cols, wT1, raw, offc_b, 256, 256, (long)CC * HW);
    gn_stats<<<NGB, 256>>>(raw, mu, rstd);
    im2col_gn_tf32<<<colsBlocks, 256>>>(raw, offc_g, offc_bt, mu, rstd, cols);
    tgemm<2><<<gPts, 128>>>(cols, wT2, pts, offo_b, 18, 32, 18L * HW);

    // ---- fork reg branch onto s2 (needs pts) ----
    cudaEventRecord(g_sh.eP, 0);
    cudaStreamWaitEvent(s2, g_sh.eP, 0);

    // reg branch on s2
    deform_cols_tf32<<<gDef, 256, 0, s2>>>(reg_feat, pts, cols2);
    tgemm<8><<<gBig, 128, 0, s2>>>(cols2, wTr, raw2, nullptr, 256, 256, (long)CC * HW);
    gn_stats<<<NGB, 256, 0, s2>>>(raw2, mu + 2 * NGB, rstd + 2 * NGB);
    gn_apply<<<gnApplyBlocks, 256, 0, s2>>>(raw2, reg_g, reg_bt,
                                            mu + 2 * NGB, rstd + 2 * NGB, reg_out);
    cudaEventRecord(g_sh.eR, s2);

    // cls branch on default stream (concurrent with s2)
    deform_cols_tf32<<<gDef, 256>>>(cls_feat, pts, cols);
    tgemm<8><<<gBig, 128>>>(cols, wTc, raw, nullptr, 256, 256, (long)CC * HW);
    gn_stats<<<NGB, 256>>>(raw, mu + NGB, rstd + NGB);
    gn_apply<<<gnApplyBlocks, 256>>>(raw, cls_g, cls_bt, mu + NGB, rstd + NGB, cls_out);

    // ---- join ----
    cudaStreamWaitEvent(0, g_sh.eR, 0);
}

// round 7
// speedup vs baseline: 2.7198x; 1.6896x over previous
#include <cuda_runtime.h>
#include <cuda_fp16.h>
#include <math.h>
#include <stdint.h>

#define BB 4
#define CC 256
#define HW 4096
#define K9 9
#define KK 2304   // 256*9
#define NG 32
#define CPG 8
#define NCHB 144  // KK/16 k-blocks

// ---------------- static scratch ----------------
__device__ __align__(16) __half g_cols[(size_t)BB * KK * HW];   // fp16 cols, [b][kk][m]
__device__ __align__(16) __half g_cols2[(size_t)BB * KK * HW];
__device__ float g_raw[BB * CC * HW];
__device__ float g_raw2[BB * CC * HW];
__device__ __align__(16) __half g_wT1[KK * 256];                // [kk][o]
__device__ __align__(16) __half g_wTc[KK * 256];
__device__ __align__(16) __half g_wTr[KK * 256];
__device__ float2 g_part[3 * BB * NG * 4];                      // per-slot partial stats
__device__ float g_mu[3 * BB * NG];
__device__ float g_rstd[3 * BB * NG];

// ---------------- streams / events ----------------
struct StreamHolder {
    cudaStream_t s1, s2;
    cudaEvent_t eF, eT, eP, eR;
    StreamHolder() {
        if (cudaStreamCreateWithFlags(&s1, cudaStreamNonBlocking) != cudaSuccess) s1 = 0;
        if (cudaStreamCreateWithFlags(&s2, cudaStreamNonBlocking) != cudaSuccess) s2 = 0;
        cudaEventCreateWithFlags(&eF, cudaEventDisableTiming);
        cudaEventCreateWithFlags(&eT, cudaEventDisableTiming);
        cudaEventCreateWithFlags(&eP, cudaEventDisableTiming);
        cudaEventCreateWithFlags(&eR, cudaEventDisableTiming);
    }
};
static StreamHolder g_sh;

// ---------------- helpers ----------------
__device__ __forceinline__ uint32_t smem_u32(const void* p) {
    uint32_t a;
    asm("{ .reg .u64 t; cvta.to.shared.u64 t, %1; cvt.u32.u64 %0, t; }"
        : "=r"(a) : "l"(p));
    return a;
}
__device__ __forceinline__ void cp16(uint32_t dst, const void* src) {
    asm volatile("cp.async.cg.shared.global [%0], [%1], 16;"
                 :: "r"(dst), "l"(src) : "memory");
}
__device__ __forceinline__ void cp_commit() {
    asm volatile("cp.async.commit_group;" ::: "memory");
}
__device__ __forceinline__ void cp_wait2() {
    asm volatile("cp.async.wait_group 2;" ::: "memory");
}
__device__ __forceinline__ void ldsm4t(uint32_t* d, uint32_t addr) {
    asm volatile("ldmatrix.sync.aligned.m8n8.x4.trans.shared.b16 {%0,%1,%2,%3}, [%4];"
        : "=r"(d[0]), "=r"(d[1]), "=r"(d[2]), "=r"(d[3]) : "r"(addr));
}
__device__ __forceinline__ void mma16816(float* d, const uint32_t* a,
                                         uint32_t b0, uint32_t b1) {
    asm volatile(
        "mma.sync.aligned.m16n8k16.row.col.f32.f16.f16.f32 "
        "{%0,%1,%2,%3},{%4,%5,%6,%7},{%8,%9},{%0,%1,%2,%3};"
        : "+f"(d[0]), "+f"(d[1]), "+f"(d[2]), "+f"(d[3])
        : "r"(a[0]), "r"(a[1]), "r"(a[2]), "r"(a[3]), "r"(b0), "r"(b1));
}

// ---------------- weight transpose -> fp16: wT[kk][o] ----------------------
__global__ void transpose_all_h(const float* __restrict__ w1, const float* __restrict__ wc,
                                const float* __restrict__ wr,
                                __half* __restrict__ o1, __half* __restrict__ oc,
                                __half* __restrict__ orr) {
    const int S = KK * 256;
    int i = blockIdx.x * 256 + threadIdx.x;
    const float* w; __half* o; int j;
    if (i < S)          { w = w1; o = o1;  j = i; }
    else if (i < 2 * S) { w = wc; o = oc;  j = i - S; }
    else                { w = wr; o = orr; j = i - 2 * S; }
    int oo = j & 255;
    int kk = j >> 8;
    int ci = kk & 255;
    int tap = kk >> 8;
    o[j] = __float2half_rn(w[(oo * CC + ci) * K9 + tap]);
}

// ---------------- im2col 3x3 pad1 -> fp16 cols[b][kk][m], 2 m per thread ----
__global__ void im2col_h(const float* __restrict__ in, __half* __restrict__ cols) {
    int idx = blockIdx.x * 256 + threadIdx.x;     // BB*KK*2048 total
    int p = idx & 2047;
    int m = p * 2;
    int r = idx >> 11;
    int kk = r % KK;
    int b = r / KK;
    int ci = kk & 255;
    int tap = kk >> 8;
    int y = (m >> 6) + tap / 3 - 1;
    int x0 = (m & 63) + tap % 3 - 1;
    float v0 = 0.f, v1 = 0.f;
    if ((unsigned)y < 64u) {
        const float* row = in + ((size_t)(b * CC + ci) * 64 + y) * 64;
        if ((unsigned)x0 < 64u) v0 = row[x0];
        if ((unsigned)(x0 + 1) < 64u) v1 = row[x0 + 1];
    }
    *(__half2*)(cols + ((size_t)(b * KK + kk)) * HW + m) =
        __floats2half2_rn(v0, v1);
}

// ---------------- deformable sampling -> fp16 cols, 2 m per thread ---------
__global__ void deform_h(const float* __restrict__ img, const float* __restrict__ pts,
                         __half* __restrict__ cols) {
    int t = blockIdx.x * 256 + threadIdx.x;       // 0..2047
    int k = blockIdx.y, b = blockIdx.z;
    int m0 = t * 2;
    float bx = (float)(k - 4);
    int i00[2], i01[2], i10[2], i11[2];
    float w00[2], w01[2], w10[2], w11[2];
#pragma unroll
    for (int e = 0; e < 2; e++) {
        int m = m0 + e;
        int y = m >> 6, x = m & 63;
        float pty = pts[(b * 18 + 2 * k) * HW + m];
        float ptx = pts[(b * 18 + 2 * k + 1) * HW + m];
        float py = pty + (float)y;
        float px = ((ptx - bx) + (float)x) + bx;
        float y0f = floorf(py), x0f = floorf(px);
        int y0 = (int)y0f, x0 = (int)x0f;
        float wy = py - y0f, wx = px - x0f;
        float a00 = (1.f - wy) * (1.f - wx);
        float a01 = (1.f - wy) * wx;
        float a10 = wy * (1.f - wx);
        float a11 = wy * wx;
        bool vy0 = (y0 >= 0) && (y0 <= 63);
        bool vy1 = (y0 + 1 >= 0) && (y0 + 1 <= 63);
        bool vx0 = (x0 >= 0) && (x0 <= 63);
        bool vx1 = (x0 + 1 >= 0) && (x0 + 1 <= 63);
        w00[e] = (vy0 && vx0) ? a00 : 0.f;
        w01[e] = (vy0 && vx1) ? a01 : 0.f;
        w10[e] = (vy1 && vx0) ? a10 : 0.f;
        w11[e] = (vy1 && vx1) ? a11 : 0.f;
        int y0c = min(max(y0, 0), 63), y1c = min(max(y0 + 1, 0), 63);
        int x0c = min(max(x0, 0), 63), x1c = min(max(x0 + 1, 0), 63);
        i00[e] = y0c * 64 + x0c; i01[e] = y0c * 64 + x1c;
        i10[e] = y1c * 64 + x0c; i11[e] = y1c * 64 + x1c;
    }
    const float* ib = img + (size_t)b * CC * HW;
    __half* cb = cols + ((size_t)b * KK + (size_t)k * CC) * HW + m0;
#pragma unroll 2
    for (int c = 0; c < CC; c++) {
        const float* ic = ib + (size_t)c * HW;
        float v0 = w00[0] * __ldg(ic + i00[0]) + w01[0] * __ldg(ic + i01[0])
                 + w10[0] * __ldg(ic + i10[0]) + w11[0] * __ldg(ic + i11[0]);
        float v1 = w00[1] * __ldg(ic + i00[1]) + w01[1] * __ldg(ic + i01[1])
                 + w10[1] * __ldg(ic + i10[1]) + w11[1] * __ldg(ic + i11[1]);
        *(__half2*)(cb + (size_t)c * HW) = __floats2half2_rn(v0, v1);
    }
}

// ---------------- GroupNorm: partial + finalize (deterministic) ------------
__global__ void gn_partial(const float* __restrict__ raw, float2* __restrict__ part) {
    int blk = blockIdx.x;                     // BB*NG*4 blocks
    int bg = blk >> 2, q = blk & 3;
    const float* p = raw + (size_t)bg * CPG * HW + q * 8192;
    float s = 0.f, ss = 0.f;
    for (int i = threadIdx.x; i < 8192; i += 256) {
        float v = p[i];
        s += v; ss += v * v;
    }
    __shared__ float sh[512];
    sh[threadIdx.x] = s;
    sh[256 + threadIdx.x] = ss;
    __syncthreads();
    for (int o = 128; o > 0; o >>= 1) {
        if (threadIdx.x < o) {
            sh[threadIdx.x] += sh[threadIdx.x + o];
            sh[256 + threadIdx.x] += sh[256 + threadIdx.x + o];
        }
        __syncthreads();
    }
    if (threadIdx.x == 0) part[blk] = make_float2(sh[0], sh[256]);
}

__global__ void gn_finalize(const float2* __restrict__ part,
                            float* __restrict__ mu, float* __restrict__ rstd) {
    int bg = threadIdx.x;                     // 128
    float s = 0.f, ss = 0.f;
#pragma unroll
    for (int q = 0; q < 4; q++) {
        float2 v = part[bg * 4 + q];
        s += v.x; ss += v.y;
    }
    const float inv_n = 1.f / (float)(CPG * HW);
    float mean = s * inv_n;
    float var = ss * inv_n - mean * mean;
    mu[bg] = mean;
    rstd[bg] = rsqrtf(var + 1e-5f);
}

__global__ void gn_apply(const float* __restrict__ raw,
                         const float* __restrict__ gamma,
                         const float* __restrict__ beta,
                         const float* __restrict__ mu,
                         const float* __restrict__ rstd,
                         float* __restrict__ out) {
    int i = blockIdx.x * 256 + threadIdx.x;
    int c = (i >> 12) & 255;
    int bg = i >> 15;
    float v = (raw[i] - mu[bg]) * rstd[bg] * gamma[c] + beta[c];
    out[i] = fmaxf(v, 0.f);
}

// ---------------- direct fp32 conv2 (GN+ReLU fused on input) ---------------
// pts[b][o][y][x] = sum_ci,ky,kx GN(raw)[b][ci][y+ky-1][x+kx-1] * w[o][ci][ky][kx] + bias
// block: 512 threads = 4 quarters x 128 pixels (2 rows of 64). 18 outputs.
__global__ void __launch_bounds__(512, 1)
conv2_direct(const float* __restrict__ raw, const float* __restrict__ gamma,
             const float* __restrict__ beta, const float* __restrict__ mu,
             const float* __restrict__ rstd, const float* __restrict__ w,
             const float* __restrict__ bias, float* __restrict__ pts) {
    __shared__ float win[4][4][64];
    __shared__ float ws[4][162];
    __shared__ float red[3][18][128];
    int b = blockIdx.z;
    int r0 = blockIdx.x * 2;
    int tid = threadIdx.x;
    int q = tid >> 7, t2 = tid & 127;
    int jb = t2 >> 6;          // pixel row within tile (0/1)
    int px = t2 & 63;

    float acc[18];
#pragma unroll
    for (int o = 0; o < 18; o++) acc[o] = 0.f;

    for (int cidx = 0; cidx < 64; cidx++) {
        int ci = q * 64 + cidx;
        __syncthreads();
        // load GN'ed window rows r0-1..r0+2 for channel ci
        float gmu = mu[b * NG + (ci >> 3)];
        float grs = rstd[b * NG + (ci >> 3)];
        float gg = gamma[ci] * grs;
        float gb = beta[ci] - gmu * gg;
        const float* rp = raw + (size_t)(b * CC + ci) * HW;
#pragma unroll
        for (int e = t2; e < 256; e += 128) {
            int j = e >> 6, x = e & 63;
            int yy = r0 - 1 + j;
            float v = 0.f;
            if ((unsigned)yy < 64u)
                v = fmaxf(rp[yy * 64 + x] * gg + gb, 0.f);
            win[q][j][x] = v;
        }
#pragma unroll
        for (int e = t2; e < 162; e += 128)
            ws[q][e] = w[((e / 9) * CC + ci) * 9 + (e % 9)];
        __syncthreads();

        float v[9];
#pragma unroll
        for (int ky = 0; ky < 3; ky++)
#pragma unroll
            for (int kx = 0; kx < 3; kx++) {
                int xx = px - 1 + kx;
                v[ky * 3 + kx] = ((unsigned)xx < 64u) ? win[q][jb + ky][xx] : 0.f;
            }
#pragma unroll
        for (int o = 0; o < 18; o++) {
            float s = acc[o];
#pragma unroll
            for (int t = 0; t < 9; t++) s += ws[q][o * 9 + t] * v[t];
            acc[o] = s;
        }
    }

    if (q > 0) {
#pragma unroll
        for (int o = 0; o < 18; o++) red[q - 1][o][t2] = acc[o];
    }
    __syncthreads();
    if (q == 0) {
        int yy = r0 + jb;
#pragma unroll
        for (int o = 0; o < 18; o++) {
            float s = acc[o] + red[0][o][t2] + red[1][o][t2] + red[2][o][t2] + bias[o];
            pts[((size_t)(b * 18 + o)) * HW + yy * 64 + px] = s;
        }
    }
}

// ---------------- fp16 mma.sync GEMM, ldmatrix + 3-stage cp.async ----------
// C[b][n][m] = sum_kk A[b][kk][m] * Bw[kk][n]; BM=128, BN=128, BK=16.
// 4 warps 2x2, 64x64 per warp. smem [k][m]/[k][n] fp16, chunk-swizzled.
__global__ void __launch_bounds__(128, 2)
tgemm_h(const __half* __restrict__ A, const __half* __restrict__ Bw,
        float* __restrict__ Cout, const float* __restrict__ bias, long cBatch) {
    __shared__ __align__(16) __half As[3][16 * 128];
    __shared__ __align__(16) __half Bs[3][16 * 128];
    int bm = blockIdx.x * 128, bn = blockIdx.y * 128, b = blockIdx.z;
    const __half* Ab = A + (size_t)b * KK * HW + bm;
    const __half* Bb = Bw + bn;
    int tid = threadIdx.x;
    int warp = tid >> 5, lane = tid & 31;
    int wm = (warp & 1) * 64, wn = (warp >> 1) * 64;
    int r = lane >> 2, c = lane & 3;

    float acc[4][8][4];
#pragma unroll
    for (int mt = 0; mt < 4; mt++)
#pragma unroll
        for (int nt = 0; nt < 8; nt++)
#pragma unroll
            for (int i = 0; i < 4; i++) acc[mt][nt][i] = 0.f;

    // ldmatrix lane roles
    int kA = (lane & 7) | ((lane & 16) >> 1);
    int cA = (lane & 8) >> 3;
    int kB = (lane & 7) | (lane & 8);
    int cB = (lane & 16) >> 4;
    uint32_t aOff[4], bOff[4];
#pragma unroll
    for (int mt = 0; mt < 4; mt++) {
        int chunk = (wm >> 3) + mt * 2 + cA;
        aOff[mt] = kA * 256 + ((chunk ^ (kA & 7)) << 4);
    }
#pragma unroll
    for (int p = 0; p < 4; p++) {
        int chunk = (wn >> 3) + p * 2 + cB;
        bOff[p] = kB * 256 + ((chunk ^ (kB & 7)) << 4);
    }

    auto stage = [&](int k0, int buf) {
#pragma unroll
        for (int s = 0; s < 2; s++) {
            int e = tid + s * 128;
            int k = e >> 4, cq = e & 15;
            uint32_t swz = (uint32_t)((cq ^ (k & 7)) << 4) + k * 256;
            cp16(smem_u32(&As[buf][0]) + swz, Ab + (size_t)(k0 + k) * HW + cq * 8);
            cp16(smem_u32(&Bs[buf][0]) + swz, Bb + (size_t)(k0 + k) * 256 + cq * 8);
        }
    };

    stage(0, 0); cp_commit();
    stage(16, 1); cp_commit();

    int buf = 0;
    for (int cc = 0; cc < NCHB; cc++) {
        if (cc + 2 < NCHB) stage((cc + 2) * 16, (cc + 2) % 3);
        cp_commit();
        cp_wait2();
        __syncthreads();
        uint32_t baseA = smem_u32(&As[buf][0]);
        uint32_t baseB = smem_u32(&Bs[buf][0]);
        uint32_t a[4][4], bb[4][4];
#pragma unroll
        for (int mt = 0; mt < 4; mt++) ldsm4t(a[mt], baseA + aOff[mt]);
#pragma unroll
        for (int p = 0; p < 4; p++) ldsm4t(bb[p], baseB + bOff[p]);
#pragma unroll
        for (int mt = 0; mt < 4; mt++)
#pragma unroll
            for (int nt = 0; nt < 8; nt++)
                mma16816(acc[mt][nt], a[mt], bb[nt >> 1][(nt & 1) * 2],
                         bb[nt >> 1][(nt & 1) * 2 + 1]);
        __syncthreads();
        buf = (buf == 2) ? 0 : buf + 1;
    }

    // epilogue: c0:(r,2c) c1:(r,2c+1) c2:(r+8,2c) c3:(r+8,2c+1)
    float* Cb = Cout + (size_t)b * cBatch;
#pragma unroll
    for (int mt = 0; mt < 4; mt++) {
        int m = bm + wm + mt * 16 + r;
#pragma unroll
        for (int nt = 0; nt < 8; nt++) {
            int n = bn + wn + nt * 8 + 2 * c;
            float bv0 = bias ? bias[n] : 0.f;
            float bv1 = bias ? bias[n + 1] : 0.f;
            Cb[(size_t)n * HW + m]           = acc[mt][nt][0] + bv0;
            Cb[(size_t)n * HW + m + 8]       = acc[mt][nt][2] + bv0;
            Cb[(size_t)(n + 1) * HW + m]     = acc[mt][nt][1] + bv1;
            Cb[(size_t)(n + 1) * HW + m + 8] = acc[mt][nt][3] + bv1;
        }
    }
}

// ---------------- launch ----------------------------------------------------
extern "C" void kernel_launch(void* const* d_in, const int* in_sizes, int n_in,
                              void* d_out, int out_size) {
    const float* cls_feat = (const float*)d_in[0];
    const float* reg_feat = (const float*)d_in[1];
    const float* offc_w   = (const float*)d_in[2];
    const float* offc_b   = (const float*)d_in[3];
    const float* offc_g   = (const float*)d_in[4];
    const float* offc_bt  = (const float*)d_in[5];
    const float* offo_w   = (const float*)d_in[6];
    const float* offo_b   = (const float*)d_in[7];
    const float* clsdc_w  = (const float*)d_in[8];
    const float* cls_g    = (const float*)d_in[9];
    const float* cls_bt   = (const float*)d_in[10];
    const float* regdc_w  = (const float*)d_in[11];
    const float* reg_g    = (const float*)d_in[12];
    const float* reg_bt   = (const float*)d_in[13];

    float* out = (float*)d_out;
    float* pts = out;                          // [4][18][4096]
    float* cls_out = out + (size_t)BB * 18 * HW;
    float* reg_out = cls_out + (size_t)BB * CC * HW;

    float *raw, *raw2, *mu, *rstd;
    float2* part;
    __half *cols, *cols2, *wT1, *wTc, *wTr;
    cudaGetSymbolAddress((void**)&cols, g_cols);
    cudaGetSymbolAddress((void**)&cols2, g_cols2);
    cudaGetSymbolAddress((void**)&raw, g_raw);
    cudaGetSymbolAddress((void**)&raw2, g_raw2);
    cudaGetSymbolAddress((void**)&wT1, g_wT1);
    cudaGetSymbolAddress((void**)&wTc, g_wTc);
    cudaGetSymbolAddress((void**)&wTr, g_wTr);
    cudaGetSymbolAddress((void**)&part, g_part);
    cudaGetSymbolAddress((void**)&mu, g_mu);
    cudaGetSymbolAddress((void**)&rstd, g_rstd);

    cudaStream_t s1 = g_sh.s1, s2 = g_sh.s2;

    const int NGB = BB * NG;                   // 128
    const int colsBlocks = (BB * KK * 2048) / 256;
    const dim3 gBig(32, 2, 4);
    const dim3 gDef(8, K9, BB);
    const dim3 gC2(32, 1, 4);
    const int gnApplyBlocks = (BB * CC * HW) / 256;

    // ---- fork: weight transposes on s1 concurrent with first im2col ----
    cudaEventRecord(g_sh.eF, 0);
    cudaStreamWaitEvent(s1, g_sh.eF, 0);
    transpose_all_h<<<(3 * KK * 256) / 256, 256, 0, s1>>>(offc_w, clsdc_w, regdc_w,
                                                          wT1, wTc, wTr);
    cudaEventRecord(g_sh.eT, s1);

    im2col_h<<<colsBlocks, 256>>>(reg_feat, cols);
    cudaStreamWaitEvent(0, g_sh.eT, 0);

    // ---- offset branch: conv1 -> GN stats -> direct conv2 -> pts ----
    tgemm_h<<<gBig, 128>>>(cols, wT1, raw, offc_b, (long)CC * HW);
    gn_partial<<<NGB * 4, 256>>>(raw, part);
    gn_finalize<<<1, NGB>>>(part, mu, rstd);
    conv2_direct<<<gC2, 512>>>(raw, offc_g, offc_bt, mu, rstd, offo_w, offo_b, pts);

    // ---- fork reg branch onto s2 (needs pts) ----
    cudaEventRecord(g_sh.eP, 0);
    cudaStreamWaitEvent(s2, g_sh.eP, 0);

    // reg branch on s2
    deform_h<<<gDef, 256, 0, s2>>>(reg_feat, pts, cols2);
    tgemm_h<<<gBig, 128, 0, s2>>>(cols2, wTr, raw2, nullptr, (long)CC * HW);
    gn_partial<<<NGB * 4, 256, 0, s2>>>(raw2, part + 2 * NGB * 4);
    gn_finalize<<<1, NGB, 0, s2>>>(part + 2 * NGB * 4, mu + 2 * NGB, rstd + 2 * NGB);
    gn_apply<<<gnApplyBlocks, 256, 0, s2>>>(raw2, reg_g, reg_bt,
                                            mu + 2 * NGB, rstd + 2 * NGB, reg_out);
    cudaEventRecord(g_sh.eR, s2);

    // cls branch on default stream
    deform_h<<<gDef, 256>>>(cls_feat, pts, cols);
    tgemm_h<<<gBig, 128>>>(cols, wTc, raw, nullptr, (long)CC * HW);
    gn_partial<<<NGB * 4, 256>>>(raw, part + NGB * 4);
    gn_finalize<<<1, NGB>>>(part + NGB * 4, mu + NGB, rstd + NGB);
    gn_apply<<<gnApplyBlocks, 256>>>(raw, cls_g, cls_bt, mu + NGB, rstd + NGB, cls_out);

    // ---- join ----
    cudaStreamWaitEvent(0, g_sh.eR, 0);
}

// round 8
// speedup vs baseline: 2.7451x; 1.0093x over previous
#include <cuda_runtime.h>
#include <cuda_fp16.h>
#include <math.h>
#include <stdint.h>

#define BB 4
#define CC 256
#define HW 4096
#define K9 9
#define KK 2304   // 256*9
#define NG 32
#define CPG 8
#define NCHB 144  // KK/16 k-blocks

// ---------------- static scratch ----------------
__device__ __align__(16) __half g_cols[(size_t)BB * KK * HW];   // fp16 cols, [b][kk][m]
__device__ __align__(16) __half g_cols2[(size_t)BB * KK * HW];
__device__ float g_raw[BB * CC * HW];
__device__ float g_raw2[BB * CC * HW];
__device__ __align__(16) __half g_wT1[KK * 256];                // [kk][o]
__device__ __align__(16) __half g_wTc[KK * 256];
__device__ __align__(16) __half g_wTr[KK * 256];
__device__ float2 g_part[3 * BB * NG * 4];                      // per-slot partial stats
__device__ float g_mu[3 * BB * NG];
__device__ float g_rstd[3 * BB * NG];

// ---------------- streams / events ----------------
struct StreamHolder {
    cudaStream_t s1, s2;
    cudaEvent_t eF, eT, eP, eR;
    StreamHolder() {
        if (cudaStreamCreateWithFlags(&s1, cudaStreamNonBlocking) != cudaSuccess) s1 = 0;
        if (cudaStreamCreateWithFlags(&s2, cudaStreamNonBlocking) != cudaSuccess) s2 = 0;
        cudaEventCreateWithFlags(&eF, cudaEventDisableTiming);
        cudaEventCreateWithFlags(&eT, cudaEventDisableTiming);
        cudaEventCreateWithFlags(&eP, cudaEventDisableTiming);
        cudaEventCreateWithFlags(&eR, cudaEventDisableTiming);
    }
};
static StreamHolder g_sh;

// ---------------- helpers ----------------
__device__ __forceinline__ uint32_t smem_u32(const void* p) {
    uint32_t a;
    asm("{ .reg .u64 t; cvta.to.shared.u64 t, %1; cvt.u32.u64 %0, t; }"
        : "=r"(a) : "l"(p));
    return a;
}
__device__ __forceinline__ void cp16(uint32_t dst, const void* src) {
    asm volatile("cp.async.cg.shared.global [%0], [%1], 16;"
                 :: "r"(dst), "l"(src) : "memory");
}
__device__ __forceinline__ void cp_commit() {
    asm volatile("cp.async.commit_group;" ::: "memory");
}
__device__ __forceinline__ void cp_wait2() {
    asm volatile("cp.async.wait_group 2;" ::: "memory");
}
__device__ __forceinline__ void ldsm4t(uint32_t* d, uint32_t addr) {
    asm volatile("ldmatrix.sync.aligned.m8n8.x4.trans.shared.b16 {%0,%1,%2,%3}, [%4];"
        : "=r"(d[0]), "=r"(d[1]), "=r"(d[2]), "=r"(d[3]) : "r"(addr));
}
__device__ __forceinline__ void mma16816(float* d, const uint32_t* a,
                                         uint32_t b0, uint32_t b1) {
    asm volatile(
        "mma.sync.aligned.m16n8k16.row.col.f32.f16.f16.f32 "
        "{%0,%1,%2,%3},{%4,%5,%6,%7},{%8,%9},{%0,%1,%2,%3};"
        : "+f"(d[0]), "+f"(d[1]), "+f"(d[2]), "+f"(d[3])
        : "r"(a[0]), "r"(a[1]), "r"(a[2]), "r"(a[3]), "r"(b0), "r"(b1));
}

// ---------------- weight transpose -> fp16: wT[kk][o] ----------------------
__global__ void transpose_all_h(const float* __restrict__ w1, const float* __restrict__ wc,
                                const float* __restrict__ wr,
                                __half* __restrict__ o1, __half* __restrict__ oc,
                                __half* __restrict__ orr) {
    const int S = KK * 256;
    int i = blockIdx.x * 256 + threadIdx.x;
    const float* w; __half* o; int j;
    if (i < S)          { w = w1; o = o1;  j = i; }
    else if (i < 2 * S) { w = wc; o = oc;  j = i - S; }
    else                { w = wr; o = orr; j = i - 2 * S; }
    int oo = j & 255;
    int kk = j >> 8;
    int ci = kk & 255;
    int tap = kk >> 8;
    o[j] = __float2half_rn(w[(oo * CC + ci) * K9 + tap]);
}

// ---------------- im2col 3x3 pad1 -> fp16 cols[b][kk][m], 2 m per thread ----
__global__ void im2col_h(const float* __restrict__ in, __half* __restrict__ cols) {
    int idx = blockIdx.x * 256 + threadIdx.x;     // BB*KK*2048 total
    int p = idx & 2047;
    int m = p * 2;
    int r = idx >> 11;
    int kk = r % KK;
    int b = r / KK;
    int ci = kk & 255;
    int tap = kk >> 8;
    int y = (m >> 6) + tap / 3 - 1;
    int x0 = (m & 63) + tap % 3 - 1;
    float v0 = 0.f, v1 = 0.f;
    if ((unsigned)y < 64u) {
        const float* row = in + ((size_t)(b * CC + ci) * 64 + y) * 64;
        if ((unsigned)x0 < 64u) v0 = row[x0];
        if ((unsigned)(x0 + 1) < 64u) v1 = row[x0 + 1];
    }
    *(__half2*)(cols + ((size_t)(b * KK + kk)) * HW + m) =
        __floats2half2_rn(v0, v1);
}

// ---------------- deformable sampling -> fp16 cols, 2 m per thread ---------
__global__ void deform_h(const float* __restrict__ img, const float* __restrict__ pts,
                         __half* __restrict__ cols) {
    int t = blockIdx.x * 256 + threadIdx.x;       // 0..2047
    int k = blockIdx.y, b = blockIdx.z;
    int m0 = t * 2;
    float bx = (float)(k - 4);
    int i00[2], i01[2], i10[2], i11[2];
    float w00[2], w01[2], w10[2], w11[2];
#pragma unroll
    for (int e = 0; e < 2; e++) {
        int m = m0 + e;
        int y = m >> 6, x = m & 63;
        float pty = pts[(b * 18 + 2 * k) * HW + m];
        float ptx = pts[(b * 18 + 2 * k + 1) * HW + m];
        float py = pty + (float)y;
        float px = ((ptx - bx) + (float)x) + bx;
        float y0f = floorf(py), x0f = floorf(px);
        int y0 = (int)y0f, x0 = (int)x0f;
        float wy = py - y0f, wx = px - x0f;
        float a00 = (1.f - wy) * (1.f - wx);
        float a01 = (1.f - wy) * wx;
        float a10 = wy * (1.f - wx);
        float a11 = wy * wx;
        bool vy0 = (y0 >= 0) && (y0 <= 63);
        bool vy1 = (y0 + 1 >= 0) && (y0 + 1 <= 63);
        bool vx0 = (x0 >= 0) && (x0 <= 63);
        bool vx1 = (x0 + 1 >= 0) && (x0 + 1 <= 63);
        w00[e] = (vy0 && vx0) ? a00 : 0.f;
        w01[e] = (vy0 && vx1) ? a01 : 0.f;
        w10[e] = (vy1 && vx0) ? a10 : 0.f;
        w11[e] = (vy1 && vx1) ? a11 : 0.f;
        int y0c = min(max(y0, 0), 63), y1c = min(max(y0 + 1, 0), 63);
        int x0c = min(max(x0, 0), 63), x1c = min(max(x0 + 1, 0), 63);
        i00[e] = y0c * 64 + x0c; i01[e] = y0c * 64 + x1c;
        i10[e] = y1c * 64 + x0c; i11[e] = y1c * 64 + x1c;
    }
    const float* ib = img + (size_t)b * CC * HW;
    __half* cb = cols + ((size_t)b * KK + (size_t)k * CC) * HW + m0;
#pragma unroll 2
    for (int c = 0; c < CC; c++) {
        const float* ic = ib + (size_t)c * HW;
        float v0 = w00[0] * __ldg(ic + i00[0]) + w01[0] * __ldg(ic + i01[0])
                 + w10[0] * __ldg(ic + i10[0]) + w11[0] * __ldg(ic + i11[0]);
        float v1 = w00[1] * __ldg(ic + i00[1]) + w01[1] * __ldg(ic + i01[1])
                 + w10[1] * __ldg(ic + i10[1]) + w11[1] * __ldg(ic + i11[1]);
        *(__half2*)(cb + (size_t)c * HW) = __floats2half2_rn(v0, v1);
    }
}

// ---------------- GroupNorm: partial + finalize (deterministic) ------------
__global__ void gn_partial(const float* __restrict__ raw, float2* __restrict__ part) {
    int blk = blockIdx.x;                     // BB*NG*4 blocks
    int bg = blk >> 2, q = blk & 3;
    const float* p = raw + (size_t)bg * CPG * HW + q * 8192;
    float s = 0.f, ss = 0.f;
    for (int i = threadIdx.x; i < 8192; i += 256) {
        float v = p[i];
        s += v; ss += v * v;
    }
    __shared__ float sh[512];
    sh[threadIdx.x] = s;
    sh[256 + threadIdx.x] = ss;
    __syncthreads();
    for (int o = 128; o > 0; o >>= 1) {
        if (threadIdx.x < o) {
            sh[threadIdx.x] += sh[threadIdx.x + o];
            sh[256 + threadIdx.x] += sh[256 + threadIdx.x + o];
        }
        __syncthreads();
    }
    if (threadIdx.x == 0) part[blk] = make_float2(sh[0], sh[256]);
}

__global__ void gn_finalize(const float2* __restrict__ part,
                            float* __restrict__ mu, float* __restrict__ rstd) {
    int bg = threadIdx.x;                     // 128
    float s = 0.f, ss = 0.f;
#pragma unroll
    for (int q = 0; q < 4; q++) {
        float2 v = part[bg * 4 + q];
        s += v.x; ss += v.y;
    }
    const float inv_n = 1.f / (float)(CPG * HW);
    float mean = s * inv_n;
    float var = ss * inv_n - mean * mean;
    mu[bg] = mean;
    rstd[bg] = rsqrtf(var + 1e-5f);
}

__global__ void gn_apply(const float* __restrict__ raw,
                         const float* __restrict__ gamma,
                         const float* __restrict__ beta,
                         const float* __restrict__ mu,
                         const float* __restrict__ rstd,
                         float* __restrict__ out) {
    int i = blockIdx.x * 256 + threadIdx.x;
    int c = (i >> 12) & 255;
    int bg = i >> 15;
    float v = (raw[i] - mu[bg]) * rstd[bg] * gamma[c] + beta[c];
    out[i] = fmaxf(v, 0.f);
}

// ---------------- direct fp32 conv2 (GN+ReLU fused on input) ---------------
// pts[b][o][y][x] = sum_ci,ky,kx GN(raw)[b][ci][y+ky-1][x+kx-1] * w[o][ci][ky][kx] + bias
// block: 512 threads = 4 quarters x 128 pixels (2 rows of 64). 18 outputs.
__global__ void __launch_bounds__(512, 1)
conv2_direct(const float* __restrict__ raw, const float* __restrict__ gamma,
             const float* __restrict__ beta, const float* __restrict__ mu,
             const float* __restrict__ rstd, const float* __restrict__ w,
             const float* __restrict__ bias, float* __restrict__ pts) {
    __shared__ float win[4][4][64];
    __shared__ float ws[4][162];
    __shared__ float red[3][18][128];
    int b = blockIdx.z;
    int r0 = blockIdx.x * 2;
    int tid = threadIdx.x;
    int q = tid >> 7, t2 = tid & 127;
    int jb = t2 >> 6;          // pixel row within tile (0/1)
    int px = t2 & 63;

    float acc[18];
#pragma unroll
    for (int o = 0; o < 18; o++) acc[o] = 0.f;

    for (int cidx = 0; cidx < 64; cidx++) {
        int ci = q * 64 + cidx;
        __syncthreads();
        // load GN'ed window rows r0-1..r0+2 for channel ci
        float gmu = mu[b * NG + (ci >> 3)];
        float grs = rstd[b * NG + (ci >> 3)];
        float gg = gamma[ci] * grs;
        float gb = beta[ci] - gmu * gg;
        const float* rp = raw + (size_t)(b * CC + ci) * HW;
#pragma unroll
        for (int e = t2; e < 256; e += 128) {
            int j = e >> 6, x = e & 63;
            int yy = r0 - 1 + j;
            float v = 0.f;
            if ((unsigned)yy < 64u)
                v = fmaxf(rp[yy * 64 + x] * gg + gb, 0.f);
            win[q][j][x] = v;
        }
#pragma unroll
        for (int e = t2; e < 162; e += 128)
            ws[q][e] = w[((e / 9) * CC + ci) * 9 + (e % 9)];
        __syncthreads();

        float v[9];
#pragma unroll
        for (int ky = 0; ky < 3; ky++)
#pragma unroll
            for (int kx = 0; kx < 3; kx++) {
                int xx = px - 1 + kx;
                v[ky * 3 + kx] = ((unsigned)xx < 64u) ? win[q][jb + ky][xx] : 0.f;
            }
#pragma unroll
        for (int o = 0; o < 18; o++) {
            float s = acc[o];
#pragma unroll
            for (int t = 0; t < 9; t++) s += ws[q][o * 9 + t] * v[t];
            acc[o] = s;
        }
    }

    if (q > 0) {
#pragma unroll
        for (int o = 0; o < 18; o++) red[q - 1][o][t2] = acc[o];
    }
    __syncthreads();
    if (q == 0) {
        int yy = r0 + jb;
#pragma unroll
        for (int o = 0; o < 18; o++) {
            float s = acc[o] + red[0][o][t2] + red[1][o][t2] + red[2][o][t2] + bias[o];
            pts[((size_t)(b * 18 + o)) * HW + yy * 64 + px] = s;
        }
    }
}

// ---------------- fp16 mma.sync GEMM, ldmatrix + 3-stage cp.async ----------
// C[b][n][m] = sum_kk A[b][kk][m] * Bw[kk][n]; BM=128, BN=128, BK=16.
// 4 warps 2x2, 64x64 per warp. smem [k][m]/[k][n] fp16, chunk-swizzled.
__global__ void __launch_bounds__(128, 2)
tgemm_h(const __half* __restrict__ A, const __half* __restrict__ Bw,
        float* __restrict__ Cout, const float* __restrict__ bias, long cBatch) {
    __shared__ __align__(16) __half As[3][16 * 128];
    __shared__ __align__(16) __half Bs[3][16 * 128];
    int bm = blockIdx.x * 128, bn = blockIdx.y * 128, b = blockIdx.z;
    const __half* Ab = A + (size_t)b * KK * HW + bm;
    const __half* Bb = Bw + bn;
    int tid = threadIdx.x;
    int warp = tid >> 5, lane = tid & 31;
    int wm = (warp & 1) * 64, wn = (warp >> 1) * 64;
    int r = lane >> 2, c = lane & 3;

    float acc[4][8][4];
#pragma unroll
    for (int mt = 0; mt < 4; mt++)
#pragma unroll
        for (int nt = 0; nt < 8; nt++)
#pragma unroll
            for (int i = 0; i < 4; i++) acc[mt][nt][i] = 0.f;

    // ldmatrix lane roles
    int kA = (lane & 7) | ((lane & 16) >> 1);
    int cA = (lane & 8) >> 3;
    int kB = (lane & 7) | (lane & 8);
    int cB = (lane & 16) >> 4;
    uint32_t aOff[4], bOff[4];
#pragma unroll
    for (int mt = 0; mt < 4; mt++) {
        int chunk = (wm >> 3) + mt * 2 + cA;
        aOff[mt] = kA * 256 + ((chunk ^ (kA & 7)) << 4);
    }
#pragma unroll
    for (int p = 0; p < 4; p++) {
        int chunk = (wn >> 3) + p * 2 + cB;
        bOff[p] = kB * 256 + ((chunk ^ (kB & 7)) << 4);
    }

    auto stage = [&](int k0, int buf) {
#pragma unroll
        for (int s = 0; s < 2; s++) {
            int e = tid + s * 128;
            int k = e >> 4, cq = e & 15;
            uint32_t swz = (uint32_t)((cq ^ (k & 7)) << 4) + k * 256;
            cp16(smem_u32(&As[buf][0]) + swz, Ab + (size_t)(k0 + k) * HW + cq * 8);
            cp16(smem_u32(&Bs[buf][0]) + swz, Bb + (size_t)(k0 + k) * 256 + cq * 8);
        }
    };

    stage(0, 0); cp_commit();
    stage(16, 1); cp_commit();

    int buf = 0;
    for (int cc = 0; cc < NCHB; cc++) {
        if (cc + 2 < NCHB) stage((cc + 2) * 16, (cc + 2) % 3);
        cp_commit();
        cp_wait2();
        __syncthreads();
        uint32_t baseA = smem_u32(&As[buf][0]);
        uint32_t baseB = smem_u32(&Bs[buf][0]);
        uint32_t a[4][4], bb[4][4];
#pragma unroll
        for (int mt = 0; mt < 4; mt++) ldsm4t(a[mt], baseA + aOff[mt]);
#pragma unroll
        for (int p = 0; p < 4; p++) ldsm4t(bb[p], baseB + bOff[p]);
#pragma unroll
        for (int mt = 0; mt < 4; mt++)
#pragma unroll
            for (int nt = 0; nt < 8; nt++)
                mma16816(acc[mt][nt], a[mt], bb[nt >> 1][(nt & 1) * 2],
                         bb[nt >> 1][(nt & 1) * 2 + 1]);
        __syncthreads();
        buf = (buf == 2) ? 0 : buf + 1;
    }

    // epilogue: c0:(r,2c) c1:(r,2c+1) c2:(r+8,2c) c3:(r+8,2c+1)
    float* Cb = Cout + (size_t)b * cBatch;
#pragma unroll
    for (int mt = 0; mt < 4; mt++) {
        int m = bm + wm + mt * 16 + r;
#pragma unroll
        for (int nt = 0; nt < 8; nt++) {
            int n = bn + wn + nt * 8 + 2 * c;
            float bv0 = bias ? bias[n] : 0.f;
            float bv1 = bias ? bias[n + 1] : 0.f;
            Cb[(size_t)n * HW + m]           = acc[mt][nt][0] + bv0;
            Cb[(size_t)n * HW + m + 8]       = acc[mt][nt][2] + bv0;
            Cb[(size_t)(n + 1) * HW + m]     = acc[mt][nt][1] + bv1;
            Cb[(size_t)(n + 1) * HW + m + 8] = acc[mt][nt][3] + bv1;
        }
    }
}

// ---------------- launch ----------------------------------------------------
extern "C" void kernel_launch(void* const* d_in, const int* in_sizes, int n_in,
                              void* d_out, int out_size) {
    const float* cls_feat = (const float*)d_in[0];
    const float* reg_feat = (const float*)d_in[1];
    const float* offc_w   = (const float*)d_in[2];
    const float* offc_b   = (const float*)d_in[3];
    const float* offc_g   = (const float*)d_in[4];
    const float* offc_bt  = (const float*)d_in[5];
    const float* offo_w   = (const float*)d_in[6];
    const float* offo_b   = (const float*)d_in[7];
    const float* clsdc_w  = (const float*)d_in[8];
    const float* cls_g    = (const float*)d_in[9];
    const float* cls_bt   = (const float*)d_in[10];
    const float* regdc_w  = (const float*)d_in[11];
    const float* reg_g    = (const float*)d_in[12];
    const float* reg_bt   = (const float*)d_in[13];

    float* out = (float*)d_out;
    float* pts = out;                          // [4][18][4096]
    float* cls_out = out + (size_t)BB * 18 * HW;
    float* reg_out = cls_out + (size_t)BB * CC * HW;

    float *raw, *raw2, *mu, *rstd;
    float2* part;
    __half *cols, *cols2, *wT1, *wTc, *wTr;
    cudaGetSymbolAddress((void**)&cols, g_cols);
    cudaGetSymbolAddress((void**)&cols2, g_cols2);
    cudaGetSymbolAddress((void**)&raw, g_raw);
    cudaGetSymbolAddress((void**)&raw2, g_raw2);
    cudaGetSymbolAddress((void**)&wT1, g_wT1);
    cudaGetSymbolAddress((void**)&wTc, g_wTc);
    cudaGetSymbolAddress((void**)&wTr, g_wTr);
    cudaGetSymbolAddress((void**)&part, g_part);
    cudaGetSymbolAddress((void**)&mu, g_mu);
    cudaGetSymbolAddress((void**)&rstd, g_rstd);

    cudaStream_t s1 = g_sh.s1, s2 = g_sh.s2;

    const int NGB = BB * NG;                   // 128
    const int colsBlocks = (BB * KK * 2048) / 256;
    const dim3 gBig(32, 2, 4);
    const dim3 gDef(8, K9, BB);
    const dim3 gC2(32, 1, 4);
    const int gnApplyBlocks = (BB * CC * HW) / 256;

    // ---- fork: weight transposes on s1 concurrent with first im2col ----
    cudaEventRecord(g_sh.eF, 0);
    cudaStreamWaitEvent(s1, g_sh.eF, 0);
    transpose_all_h<<<(3 * KK * 256) / 256, 256, 0, s1>>>(offc_w, clsdc_w, regdc_w,
                                                          wT1, wTc, wTr);
    cudaEventRecord(g_sh.eT, s1);

    im2col_h<<<colsBlocks, 256>>>(reg_feat, cols);
    cudaStreamWaitEvent(0, g_sh.eT, 0);

    // ---- offset branch: conv1 -> GN stats -> direct conv2 -> pts ----
    tgemm_h<<<gBig, 128>>>(cols, wT1, raw, offc_b, (long)CC * HW);
    gn_partial<<<NGB * 4, 256>>>(raw, part);
    gn_finalize<<<1, NGB>>>(part, mu, rstd);
    conv2_direct<<<gC2, 512>>>(raw, offc_g, offc_bt, mu, rstd, offo_w, offo_b, pts);

    // ---- fork reg branch onto s2 (needs pts) ----
    cudaEventRecord(g_sh.eP, 0);
    cudaStreamWaitEvent(s2, g_sh.eP, 0);

    // reg branch on s2
    deform_h<<<gDef, 256, 0, s2>>>(reg_feat, pts, cols2);
    tgemm_h<<<gBig, 128, 0, s2>>>(cols2, wTr, raw2, nullptr, (long)CC * HW);
    gn_partial<<<NGB * 4, 256, 0, s2>>>(raw2, part + 2 * NGB * 4);
    gn_finalize<<<1, NGB, 0, s2>>>(part + 2 * NGB * 4, mu + 2 * NGB, rstd + 2 * NGB);
    gn_apply<<<gnApplyBlocks, 256, 0, s2>>>(raw2, reg_g, reg_bt,
                                            mu + 2 * NGB, rstd + 2 * NGB, reg_out);
    cudaEventRecord(g_sh.eR, s2);

    // cls branch on default stream
    deform_h<<<gDef, 256>>>(cls_feat, pts, cols);
    tgemm_h<<<gBig, 128>>>(cols, wTc, raw, nullptr, (long)CC * HW);
    gn_partial<<<NGB * 4, 256>>>(raw, part + NGB * 4);
    gn_finalize<<<1, NGB>>>(part + NGB * 4, mu + NGB, rstd + NGB);
    gn_apply<<<gnApplyBlocks, 256>>>(raw, cls_g, cls_bt, mu + NGB, rstd + NGB, cls_out);

    // ---- join ----
    cudaStreamWaitEvent(0, g_sh.eR, 0);
}

// round 9
// speedup vs baseline: 2.7509x; 1.0021x over previous
#include <cuda_runtime.h>
#include <cuda_fp16.h>
#include <math.h>
#include <stdint.h>

#define BB 4
#define CC 256
#define HW 4096
#define K9 9
#define KK 2304   // 256*9
#define NG 32
#define CPG 8
#define NCHB 144  // KK/16 k-blocks

// ---------------- static scratch ----------------
__device__ __align__(16) __half g_cols[(size_t)BB * KK * HW];   // fp16 cols, [b][kk][m]
__device__ __align__(16) __half g_cols2[(size_t)BB * KK * HW];
__device__ float g_raw[BB * CC * HW];
__device__ float g_raw2[BB * CC * HW];
__device__ __align__(16) __half g_wT1[KK * 256];                // [kk][o]
__device__ __align__(16) __half g_wTc[KK * 256];
__device__ __align__(16) __half g_wTr[KK * 256];
__device__ float2 g_part[3 * BB * NG * 4];                      // per-slot partial stats
__device__ float g_mu[3 * BB * NG];
__device__ float g_rstd[3 * BB * NG];

// ---------------- streams / events ----------------
struct StreamHolder {
    cudaStream_t s1, s2;
    cudaEvent_t eF, eT, eP, eR;
    StreamHolder() {
        if (cudaStreamCreateWithFlags(&s1, cudaStreamNonBlocking) != cudaSuccess) s1 = 0;
        if (cudaStreamCreateWithFlags(&s2, cudaStreamNonBlocking) != cudaSuccess) s2 = 0;
        cudaEventCreateWithFlags(&eF, cudaEventDisableTiming);
        cudaEventCreateWithFlags(&eT, cudaEventDisableTiming);
        cudaEventCreateWithFlags(&eP, cudaEventDisableTiming);
        cudaEventCreateWithFlags(&eR, cudaEventDisableTiming);
    }
};
static StreamHolder g_sh;

// ---------------- helpers ----------------
__device__ __forceinline__ uint32_t smem_u32(const void* p) {
    uint32_t a;
    asm("{ .reg .u64 t; cvta.to.shared.u64 t, %1; cvt.u32.u64 %0, t; }"
        : "=r"(a) : "l"(p));
    return a;
}
__device__ __forceinline__ void cp16(uint32_t dst, const void* src) {
    asm volatile("cp.async.cg.shared.global [%0], [%1], 16;"
                 :: "r"(dst), "l"(src) : "memory");
}
__device__ __forceinline__ void cp_commit() {
    asm volatile("cp.async.commit_group;" ::: "memory");
}
__device__ __forceinline__ void cp_wait2() {
    asm volatile("cp.async.wait_group 2;" ::: "memory");
}
__device__ __forceinline__ void ldsm4t(uint32_t* d, uint32_t addr) {
    asm volatile("ldmatrix.sync.aligned.m8n8.x4.trans.shared.b16 {%0,%1,%2,%3}, [%4];"
        : "=r"(d[0]), "=r"(d[1]), "=r"(d[2]), "=r"(d[3]) : "r"(addr));
}
__device__ __forceinline__ void mma16816(float* d, const uint32_t* a,
                                         uint32_t b0, uint32_t b1) {
    asm volatile(
        "mma.sync.aligned.m16n8k16.row.col.f32.f16.f16.f32 "
        "{%0,%1,%2,%3},{%4,%5,%6,%7},{%8,%9},{%0,%1,%2,%3};"
        : "+f"(d[0]), "+f"(d[1]), "+f"(d[2]), "+f"(d[3])
        : "r"(a[0]), "r"(a[1]), "r"(a[2]), "r"(a[3]), "r"(b0), "r"(b1));
}

// ---------------- weight transpose -> fp16: wT[kk][o] ----------------------
__global__ void transpose_all_h(const float* __restrict__ w1, const float* __restrict__ wc,
                                const float* __restrict__ wr,
                                __half* __restrict__ o1, __half* __restrict__ oc,
                                __half* __restrict__ orr) {
    const int S = KK * 256;
    int i = blockIdx.x * 256 + threadIdx.x;
    const float* w; __half* o; int j;
    if (i < S)          { w = w1; o = o1;  j = i; }
    else if (i < 2 * S) { w = wc; o = oc;  j = i - S; }
    else                { w = wr; o = orr; j = i - 2 * S; }
    int oo = j & 255;
    int kk = j >> 8;
    int ci = kk & 255;
    int tap = kk >> 8;
    o[j] = __float2half_rn(w[(oo * CC + ci) * K9 + tap]);
}

// ---------------- im2col 3x3 pad1 -> fp16 cols[b][kk][m], 2 m per thread ----
__global__ void im2col_h(const float* __restrict__ in, __half* __restrict__ cols) {
    int idx = blockIdx.x * 256 + threadIdx.x;     // BB*KK*2048 total
    int p = idx & 2047;
    int m = p * 2;
    int r = idx >> 11;
    int kk = r % KK;
    int b = r / KK;
    int ci = kk & 255;
    int tap = kk >> 8;
    int y = (m >> 6) + tap / 3 - 1;
    int x0 = (m & 63) + tap % 3 - 1;
    float v0 = 0.f, v1 = 0.f;
    if ((unsigned)y < 64u) {
        const float* row = in + ((size_t)(b * CC + ci) * 64 + y) * 64;
        if ((unsigned)x0 < 64u) v0 = row[x0];
        if ((unsigned)(x0 + 1) < 64u) v1 = row[x0 + 1];
    }
    *(__half2*)(cols + ((size_t)(b * KK + kk)) * HW + m) =
        __floats2half2_rn(v0, v1);
}

// ---------------- deformable sampling -> fp16 cols, 2 m per thread ---------
__global__ void deform_h(const float* __restrict__ img, const float* __restrict__ pts,
                         __half* __restrict__ cols) {
    int t = blockIdx.x * 256 + threadIdx.x;       // 0..2047
    int k = blockIdx.y, b = blockIdx.z;
    int m0 = t * 2;
    float bx = (float)(k - 4);
    int i00[2], i01[2], i10[2], i11[2];
    float w00[2], w01[2], w10[2], w11[2];
#pragma unroll
    for (int e = 0; e < 2; e++) {
        int m = m0 + e;
        int y = m >> 6, x = m & 63;
        float pty = pts[(b * 18 + 2 * k) * HW + m];
        float ptx = pts[(b * 18 + 2 * k + 1) * HW + m];
        float py = pty + (float)y;
        float px = ((ptx - bx) + (float)x) + bx;
        float y0f = floorf(py), x0f = floorf(px);
        int y0 = (int)y0f, x0 = (int)x0f;
        float wy = py - y0f, wx = px - x0f;
        float a00 = (1.f - wy) * (1.f - wx);
        float a01 = (1.f - wy) * wx;
        float a10 = wy * (1.f - wx);
        float a11 = wy * wx;
        bool vy0 = (y0 >= 0) && (y0 <= 63);
        bool vy1 = (y0 + 1 >= 0) && (y0 + 1 <= 63);
        bool vx0 = (x0 >= 0) && (x0 <= 63);
        bool vx1 = (x0 + 1 >= 0) && (x0 + 1 <= 63);
        w00[e] = (vy0 && vx0) ? a00 : 0.f;
        w01[e] = (vy0 && vx1) ? a01 : 0.f;
        w10[e] = (vy1 && vx0) ? a10 : 0.f;
        w11[e] = (vy1 && vx1) ? a11 : 0.f;
        int y0c = min(max(y0, 0), 63), y1c = min(max(y0 + 1, 0), 63);
        int x0c = min(max(x0, 0), 63), x1c = min(max(x0 + 1, 0), 63);
        i00[e] = y0c * 64 + x0c; i01[e] = y0c * 64 + x1c;
        i10[e] = y1c * 64 + x0c; i11[e] = y1c * 64 + x1c;
    }
    const float* ib = img + (size_t)b * CC * HW;
    __half* cb = cols + ((size_t)b * KK + (size_t)k * CC) * HW + m0;
#pragma unroll 2
    for (int c = 0; c < CC; c++) {
        const float* ic = ib + (size_t)c * HW;
        float v0 = w00[0] * __ldg(ic + i00[0]) + w01[0] * __ldg(ic + i01[0])
                 + w10[0] * __ldg(ic + i10[0]) + w11[0] * __ldg(ic + i11[0]);
        float v1 = w00[1] * __ldg(ic + i00[1]) + w01[1] * __ldg(ic + i01[1])
                 + w10[1] * __ldg(ic + i10[1]) + w11[1] * __ldg(ic + i11[1]);
        *(__half2*)(cb + (size_t)c * HW) = __floats2half2_rn(v0, v1);
    }
}

// ---------------- GroupNorm: partial + finalize (deterministic) ------------
__global__ void gn_partial(const float* __restrict__ raw, float2* __restrict__ part) {
    int blk = blockIdx.x;                     // BB*NG*4 blocks
    int bg = blk >> 2, q = blk & 3;
    const float* p = raw + (size_t)bg * CPG * HW + q * 8192;
    float s = 0.f, ss = 0.f;
    for (int i = threadIdx.x; i < 8192; i += 256) {
        float v = p[i];
        s += v; ss += v * v;
    }
    __shared__ float sh[512];
    sh[threadIdx.x] = s;
    sh[256 + threadIdx.x] = ss;
    __syncthreads();
    for (int o = 128; o > 0; o >>= 1) {
        if (threadIdx.x < o) {
            sh[threadIdx.x] += sh[threadIdx.x + o];
            sh[256 + threadIdx.x] += sh[256 + threadIdx.x + o];
        }
        __syncthreads();
    }
    if (threadIdx.x == 0) part[blk] = make_float2(sh[0], sh[256]);
}

__global__ void gn_finalize(const float2* __restrict__ part,
                            float* __restrict__ mu, float* __restrict__ rstd) {
    int bg = threadIdx.x;                     // 128
    float s = 0.f, ss = 0.f;
#pragma unroll
    for (int q = 0; q < 4; q++) {
        float2 v = part[bg * 4 + q];
        s += v.x; ss += v.y;
    }
    const float inv_n = 1.f / (float)(CPG * HW);
    float mean = s * inv_n;
    float var = ss * inv_n - mean * mean;
    mu[bg] = mean;
    rstd[bg] = rsqrtf(var + 1e-5f);
}

__global__ void gn_apply(const float* __restrict__ raw,
                         const float* __restrict__ gamma,
                         const float* __restrict__ beta,
                         const float* __restrict__ mu,
                         const float* __restrict__ rstd,
                         float* __restrict__ out) {
    int i = blockIdx.x * 256 + threadIdx.x;
    int c = (i >> 12) & 255;
    int bg = i >> 15;
    float v = (raw[i] - mu[bg]) * rstd[bg] * gamma[c] + beta[c];
    out[i] = fmaxf(v, 0.f);
}

// ---------------- direct fp32 conv2 (GN+ReLU fused on input) ---------------
// pts[b][o][y][x] = sum_ci,ky,kx GN(raw)[b][ci][y+ky-1][x+kx-1] * w[o][ci][ky][kx] + bias
// block: 512 threads = 4 quarters x 128 pixels (2 rows of 64). 18 outputs.
__global__ void __launch_bounds__(512, 1)
conv2_direct(const float* __restrict__ raw, const float* __restrict__ gamma,
             const float* __restrict__ beta, const float* __restrict__ mu,
             const float* __restrict__ rstd, const float* __restrict__ w,
             const float* __restrict__ bias, float* __restrict__ pts) {
    __shared__ float win[4][4][64];
    __shared__ float ws[4][162];
    __shared__ float red[3][18][128];
    int b = blockIdx.z;
    int r0 = blockIdx.x * 2;
    int tid = threadIdx.x;
    int q = tid >> 7, t2 = tid & 127;
    int jb = t2 >> 6;          // pixel row within tile (0/1)
    int px = t2 & 63;

    float acc[18];
#pragma unroll
    for (int o = 0; o < 18; o++) acc[o] = 0.f;

    for (int cidx = 0; cidx < 64; cidx++) {
        int ci = q * 64 + cidx;
        __syncthreads();
        // load GN'ed window rows r0-1..r0+2 for channel ci
        float gmu = mu[b * NG + (ci >> 3)];
        float grs = rstd[b * NG + (ci >> 3)];
        float gg = gamma[ci] * grs;
        float gb = beta[ci] - gmu * gg;
        const float* rp = raw + (size_t)(b * CC + ci) * HW;
#pragma unroll
        for (int e = t2; e < 256; e += 128) {
            int j = e >> 6, x = e & 63;
            int yy = r0 - 1 + j;
            float v = 0.f;
            if ((unsigned)yy < 64u)
                v = fmaxf(rp[yy * 64 + x] * gg + gb, 0.f);
            win[q][j][x] = v;
        }
#pragma unroll
        for (int e = t2; e < 162; e += 128)
            ws[q][e] = w[((e / 9) * CC + ci) * 9 + (e % 9)];
        __syncthreads();

        float v[9];
#pragma unroll
        for (int ky = 0; ky < 3; ky++)
#pragma unroll
            for (int kx = 0; kx < 3; kx++) {
                int xx = px - 1 + kx;
                v[ky * 3 + kx] = ((unsigned)xx < 64u) ? win[q][jb + ky][xx] : 0.f;
            }
#pragma unroll
        for (int o = 0; o < 18; o++) {
            float s = acc[o];
#pragma unroll
            for (int t = 0; t < 9; t++) s += ws[q][o * 9 + t] * v[t];
            acc[o] = s;
        }
    }

    if (q > 0) {
#pragma unroll
        for (int o = 0; o < 18; o++) red[q - 1][o][t2] = acc[o];
    }
    __syncthreads();
    if (q == 0) {
        int yy = r0 + jb;
#pragma unroll
        for (int o = 0; o < 18; o++) {
            float s = acc[o] + red[0][o][t2] + red[1][o][t2] + red[2][o][t2] + bias[o];
            pts[((size_t)(b * 18 + o)) * HW + yy * 64 + px] = s;
        }
    }
}

// ---------------- fp16 mma.sync GEMM, ldmatrix + 3-stage cp.async ----------
// C[b][n][m] = sum_kk A[b][kk][m] * Bw[kk][n]; BM=128, BN=128, BK=16.
// 4 warps 2x2, 64x64 per warp. smem [k][m]/[k][n] fp16, chunk-swizzled.
__global__ void __launch_bounds__(128, 2)
tgemm_h(const __half* __restrict__ A, const __half* __restrict__ Bw,
        float* __restrict__ Cout, const float* __restrict__ bias, long cBatch) {
    __shared__ __align__(16) __half As[3][16 * 128];
    __shared__ __align__(16) __half Bs[3][16 * 128];
    int bm = blockIdx.x * 128, bn = blockIdx.y * 128, b = blockIdx.z;
    const __half* Ab = A + (size_t)b * KK * HW + bm;
    const __half* Bb = Bw + bn;
    int tid = threadIdx.x;
    int warp = tid >> 5, lane = tid & 31;
    int wm = (warp & 1) * 64, wn = (warp >> 1) * 64;
    int r = lane >> 2, c = lane & 3;

    float acc[4][8][4];
#pragma unroll
    for (int mt = 0; mt < 4; mt++)
#pragma unroll
        for (int nt = 0; nt < 8; nt++)
#pragma unroll
            for (int i = 0; i < 4; i++) acc[mt][nt][i] = 0.f;

    // ldmatrix lane roles
    int kA = (lane & 7) | ((lane & 16) >> 1);
    int cA = (lane & 8) >> 3;
    int kB = (lane & 7) | (lane & 8);
    int cB = (lane & 16) >> 4;
    uint32_t aOff[4], bOff[4];
#pragma unroll
    for (int mt = 0; mt < 4; mt++) {
        int chunk = (wm >> 3) + mt * 2 + cA;
        aOff[mt] = kA * 256 + ((chunk ^ (kA & 7)) << 4);
    }
#pragma unroll
    for (int p = 0; p < 4; p++) {
        int chunk = (wn >> 3) + p * 2 + cB;
        bOff[p] = kB * 256 + ((chunk ^ (kB & 7)) << 4);
    }

    auto stage = [&](int k0, int buf) {
#pragma unroll
        for (int s = 0; s < 2; s++) {
            int e = tid + s * 128;
            int k = e >> 4, cq = e & 15;
            uint32_t swz = (uint32_t)((cq ^ (k & 7)) << 4) + k * 256;
            cp16(smem_u32(&As[buf][0]) + swz, Ab + (size_t)(k0 + k) * HW + cq * 8);
            cp16(smem_u32(&Bs[buf][0]) + swz, Bb + (size_t)(k0 + k) * 256 + cq * 8);
        }
    };

    stage(0, 0); cp_commit();
    stage(16, 1); cp_commit();

    int buf = 0;
    for (int cc = 0; cc < NCHB; cc++) {
        if (cc + 2 < NCHB) stage((cc + 2) * 16, (cc + 2) % 3);
        cp_commit();
        cp_wait2();
        __syncthreads();
        uint32_t baseA = smem_u32(&As[buf][0]);
        uint32_t baseB = smem_u32(&Bs[buf][0]);
        uint32_t a[4][4], bb[4][4];
#pragma unroll
        for (int mt = 0; mt < 4; mt++) ldsm4t(a[mt], baseA + aOff[mt]);
#pragma unroll
        for (int p = 0; p < 4; p++) ldsm4t(bb[p], baseB + bOff[p]);
#pragma unroll
        for (int mt = 0; mt < 4; mt++)
#pragma unroll
            for (int nt = 0; nt < 8; nt++)
                mma16816(acc[mt][nt], a[mt], bb[nt >> 1][(nt & 1) * 2],
                         bb[nt >> 1][(nt & 1) * 2 + 1]);
        __syncthreads();
        buf = (buf == 2) ? 0 : buf + 1;
    }

    // epilogue: c0:(r,2c) c1:(r,2c+1) c2:(r+8,2c) c3:(r+8,2c+1)
    float* Cb = Cout + (size_t)b * cBatch;
#pragma unroll
    for (int mt = 0; mt < 4; mt++) {
        int m = bm + wm + mt * 16 + r;
#pragma unroll
        for (int nt = 0; nt < 8; nt++) {
            int n = bn + wn + nt * 8 + 2 * c;
            float bv0 = bias ? bias[n] : 0.f;
            float bv1 = bias ? bias[n + 1] : 0.f;
            Cb[(size_t)n * HW + m]           = acc[mt][nt][0] + bv0;
            Cb[(size_t)n * HW + m + 8]       = acc[mt][nt][2] + bv0;
            Cb[(size_t)(n + 1) * HW + m]     = acc[mt][nt][1] + bv1;
            Cb[(size_t)(n + 1) * HW + m + 8] = acc[mt][nt][3] + bv1;
        }
    }
}

// ---------------- launch ----------------------------------------------------
extern "C" void kernel_launch(void* const* d_in, const int* in_sizes, int n_in,
                              void* d_out, int out_size) {
    const float* cls_feat = (const float*)d_in[0];
    const float* reg_feat = (const float*)d_in[1];
    const float* offc_w   = (const float*)d_in[2];
    const float* offc_b   = (const float*)d_in[3];
    const float* offc_g   = (const float*)d_in[4];
    const float* offc_bt  = (const float*)d_in[5];
    const float* offo_w   = (const float*)d_in[6];
    const float* offo_b   = (const float*)d_in[7];
    const float* clsdc_w  = (const float*)d_in[8];
    const float* cls_g    = (const float*)d_in[9];
    const float* cls_bt   = (const float*)d_in[10];
    const float* regdc_w  = (const float*)d_in[11];
    const float* reg_g    = (const float*)d_in[12];
    const float* reg_bt   = (const float*)d_in[13];

    float* out = (float*)d_out;
    float* pts = out;                          // [4][18][4096]
    float* cls_out = out + (size_t)BB * 18 * HW;
    float* reg_out = cls_out + (size_t)BB * CC * HW;

    float *raw, *raw2, *mu, *rstd;
    float2* part;
    __half *cols, *cols2, *wT1, *wTc, *wTr;
    cudaGetSymbolAddress((void**)&cols, g_cols);
    cudaGetSymbolAddress((void**)&cols2, g_cols2);
    cudaGetSymbolAddress((void**)&raw, g_raw);
    cudaGetSymbolAddress((void**)&raw2, g_raw2);
    cudaGetSymbolAddress((void**)&wT1, g_wT1);
    cudaGetSymbolAddress((void**)&wTc, g_wTc);
    cudaGetSymbolAddress((void**)&wTr, g_wTr);
    cudaGetSymbolAddress((void**)&part, g_part);
    cudaGetSymbolAddress((void**)&mu, g_mu);
    cudaGetSymbolAddress((void**)&rstd, g_rstd);

    cudaStream_t s1 = g_sh.s1, s2 = g_sh.s2;

    const int NGB = BB * NG;                   // 128
    const int colsBlocks = (BB * KK * 2048) / 256;
    const dim3 gBig(32, 2, 4);
    const dim3 gDef(8, K9, BB);
    const dim3 gC2(32, 1, 4);
    const int gnApplyBlocks = (BB * CC * HW) / 256;

    // ---- fork: weight transposes on s1 concurrent with first im2col ----
    cudaEventRecord(g_sh.eF, 0);
    cudaStreamWaitEvent(s1, g_sh.eF, 0);
    transpose_all_h<<<(3 * KK * 256) / 256, 256, 0, s1>>>(offc_w, clsdc_w, regdc_w,
                                                          wT1, wTc, wTr);
    cudaEventRecord(g_sh.eT, s1);

    im2col_h<<<colsBlocks, 256>>>(reg_feat, cols);
    cudaStreamWaitEvent(0, g_sh.eT, 0);

    // ---- offset branch: conv1 -> GN stats -> direct conv2 -> pts ----
    tgemm_h<<<gBig, 128>>>(cols, wT1, raw, offc_b, (long)CC * HW);
    gn_partial<<<NGB * 4, 256>>>(raw, part);
    gn_finalize<<<1, NGB>>>(part, mu, rstd);
    conv2_direct<<<gC2, 512>>>(raw, offc_g, offc_bt, mu, rstd, offo_w, offo_b, pts);

    // ---- fork reg branch onto s2 (needs pts) ----
    cudaEventRecord(g_sh.eP, 0);
    cudaStreamWaitEvent(s2, g_sh.eP, 0);

    // reg branch on s2
    deform_h<<<gDef, 256, 0, s2>>>(reg_feat, pts, cols2);
    tgemm_h<<<gBig, 128, 0, s2>>>(cols2, wTr, raw2, nullptr, (long)CC * HW);
    gn_partial<<<NGB * 4, 256, 0, s2>>>(raw2, part + 2 * NGB * 4);
    gn_finalize<<<1, NGB, 0, s2>>>(part + 2 * NGB * 4, mu + 2 * NGB, rstd + 2 * NGB);
    gn_apply<<<gnApplyBlocks, 256, 0, s2>>>(raw2, reg_g, reg_bt,
                                            mu + 2 * NGB, rstd + 2 * NGB, reg_out);
    cudaEventRecord(g_sh.eR, s2);

    // cls branch on default stream
    deform_h<<<gDef, 256>>>(cls_feat, pts, cols);
    tgemm_h<<<gBig, 128>>>(cols, wTc, raw, nullptr, (long)CC * HW);
    gn_partial<<<NGB * 4, 256>>>(raw, part + NGB * 4);
    gn_finalize<<<1, NGB>>>(part + NGB * 4, mu + NGB, rstd + NGB);
    gn_apply<<<gnApplyBlocks, 256>>>(raw, cls_g, cls_bt, mu + NGB, rstd + NGB, cls_out);

    // ---- join ----
    cudaStreamWaitEvent(0, g_sh.eR, 0);
}